// round 10
// baseline (speedup 1.0000x reference)
#include <cuda_runtime.h>
#include <cuda_bf16.h>
#include <cstdint>
#include <cstddef>

// Problem constants
#define TT 2048
#define BB 2
#define EE 1024
#define HH 16
#define HK 64          // head dim
#define FFD 4096
#define MM (TT*BB)     // 4096 rows
#define LN_EPS 1e-5f
#define BK8 8          // GEMM K chunk
#define P12 12         // GEMM smem pitch (floats); conflict-free
#define KPITCH 68      // attention K-tile pitch
#define VPITCH 72      // attention V-tile pitch

// ---------------------------------------------------------------------------
// Scratch (device globals; no allocation allowed)
// ---------------------------------------------------------------------------
__device__ float g_keep[MM];
__device__ int   g_maskmode;
__device__ float g_q[MM * EE];
__device__ float g_k[MM * EE];
__device__ float g_v[MM * EE];
__device__ float g_ctx[MM * EE];
__device__ float g_t1[MM * EE];
__device__ float g_s1[MM * EE];      // LN1 out (residual + FFN1 A)
__device__ float g_hid[(size_t)MM * FFD];
__device__ float g_t2[MM * EE];

// ---------------------------------------------------------------------------
// Helpers
// ---------------------------------------------------------------------------
__device__ __forceinline__ uint32_t smem_u32(const void* p) {
    uint32_t a;
    asm("{ .reg .u64 t; cvta.to.shared.u64 t, %1; cvt.u32.u64 %0, t; }"
        : "=r"(a) : "l"(p));
    return a;
}

__device__ __forceinline__ uint32_t f2tf32(float x) {
    uint32_t r;
    asm("cvt.rna.tf32.f32 %0, %1;" : "=r"(r) : "f"(x));
    return r;
}
__device__ __forceinline__ float f2tf32f(float x) {
    return __uint_as_float(f2tf32(x));
}

#define CP_ASYNC16(dst_u32, src_ptr) \
    asm volatile("cp.async.cg.shared.global [%0], [%1], 16;" \
                 :: "r"(dst_u32), "l"(src_ptr) : "memory")
#define CP_COMMIT asm volatile("cp.async.commit_group;" ::: "memory")
#define CP_WAIT2  asm volatile("cp.async.wait_group 2;" ::: "memory")
#define CP_WAIT1  asm volatile("cp.async.wait_group 1;" ::: "memory")
#define CP_WAIT0  asm volatile("cp.async.wait_group 0;" ::: "memory")

#define MMA_TF32(c, a, b) \
    asm volatile("mma.sync.aligned.m16n8k8.row.col.f32.tf32.tf32.f32 " \
        "{%0,%1,%2,%3}, {%4,%5,%6,%7}, {%8,%9}, {%0,%1,%2,%3};" \
        : "+f"((c)[0]), "+f"((c)[1]), "+f"((c)[2]), "+f"((c)[3]) \
        : "r"((a)[0]), "r"((a)[1]), "r"((a)[2]), "r"((a)[3]), \
          "r"((b)[0]), "r"((b)[1]))

// ---------------------------------------------------------------------------
// Mask dtype detection + keep vector
// ---------------------------------------------------------------------------
__global__ void detect_mask_kernel(const unsigned char* __restrict__ mask) {
    __shared__ int cnt[4];
    if (threadIdx.x < 4) cnt[threadIdx.x] = 0;
    __syncthreads();
    for (int i = threadIdx.x; i < BB * TT; i += blockDim.x) {
        if (mask[i]) atomicAdd(&cnt[i & 3], 1);
    }
    __syncthreads();
    if (threadIdx.x == 0) {
        int mode;
        if (cnt[1] > 0)                    mode = 0;  // bytes
        else if (cnt[2] > 0 || cnt[3] > 0) mode = 2;  // float32
        else if (cnt[0] > 0)               mode = 1;  // int32
        else                               mode = 3;  // all zero
        g_maskmode = mode;
    }
}

__global__ void build_keep_kernel(const void* __restrict__ mask) {
    int m = blockIdx.x * blockDim.x + threadIdx.x;
    if (m >= MM) return;
    int t = m >> 1;
    int b = m & 1;
    int idx = b * TT + t;
    int mode = g_maskmode;
    bool pad;
    if (mode == 0)      pad = ((const unsigned char*)mask)[idx] != 0;
    else if (mode == 1) pad = ((const int*)mask)[idx] != 0;
    else if (mode == 2) pad = ((const float*)mask)[idx] != 0.0f;
    else                pad = false;
    g_keep[m] = pad ? 0.0f : 1.0f;
}

// ---------------------------------------------------------------------------
// tf32 mma.sync NT GEMM:  C[M,N] = epi( rowscale[m]*(A[M,K]*B[N,K]^T) + bias[N] )
//   EPI 0: + bias; EPI 1: + bias, ReLU; EPI 2: + bias + residual
// Deep pipeline: CTA tile 128x128, BK=8, 4-stage cp.async (48KB static smem),
// ONE syncthreads per chunk, prefetch depth 3. 8 warps (2Mx4N), warp 64x32.
// Pitch-12: conflict-free for 16B cp.async stores (8-thread phases hit all 32
// banks) and for fragment LDS (12r mod 32 over r=0..7 is a permutation).
// Fragments rounded to tf32 (rna) after LDS — bit-identical to pre-rounding.
// ---------------------------------------------------------------------------
template <int EPI>
__global__ void __launch_bounds__(256, 2)
gemm_mma_kernel(const float* __restrict__ A, const float* __restrict__ Bw,
                const float* __restrict__ bias, const float* __restrict__ rowscale,
                const float* __restrict__ res, float* __restrict__ C,
                int Ndim, int Kdim) {
    __shared__ __align__(16) float sA[4][128 * P12];
    __shared__ __align__(16) float sB[4][128 * P12];

    const int tid = threadIdx.x;
    const int wid = tid >> 5;
    const int lid = tid & 31;
    const int m0 = blockIdx.y * 128;
    const int n0 = blockIdx.x * 128;
    const int wm = (wid >> 2) * 64;   // warp M offset
    const int wn = (wid & 3) * 32;    // warp N offset
    const int lm = lid >> 2;          // 0..7
    const int lk = lid & 3;           // 0..3

    // Staging: thread -> (row = tid&127, 16B group = tid>>7) for A and B.
    const int srow = tid & 127;
    const int sg   = (tid >> 7) * 4;  // float offset 0 or 4
    const float* Agp = A  + (size_t)(m0 + srow) * Kdim + sg;
    const float* Bgp = Bw + (size_t)(n0 + srow) * Kdim + sg;
    const uint32_t dA0 = smem_u32(&sA[0][srow * P12 + sg]);
    const uint32_t dB0 = smem_u32(&sB[0][srow * P12 + sg]);
    const uint32_t stageBytes = 128 * P12 * 4;

    float acc[4][4][4];
    #pragma unroll
    for (int mt = 0; mt < 4; mt++)
        #pragma unroll
        for (int nt = 0; nt < 4; nt++)
            #pragma unroll
            for (int r = 0; r < 4; r++) acc[mt][nt][r] = 0.0f;

    const int nch = Kdim >> 3;

    // Prologue: stage chunks 0,1,2
    #pragma unroll
    for (int p = 0; p < 3; p++) {
        CP_ASYNC16(dA0 + p * stageBytes, Agp + p * BK8);
        CP_ASYNC16(dB0 + p * stageBytes, Bgp + p * BK8);
        CP_COMMIT;
    }

    for (int c = 0; c < nch; c++) {
        if (c + 2 < nch)      { CP_WAIT2; }
        else if (c + 1 < nch) { CP_WAIT1; }
        else                  { CP_WAIT0; }
        __syncthreads();      // chunk c visible to all; stage (c+3)%4 free
        if (c + 3 < nch) {
            const uint32_t bs = ((c + 3) & 3) * stageBytes;
            CP_ASYNC16(dA0 + bs, Agp + (c + 3) * BK8);
            CP_ASYNC16(dB0 + bs, Bgp + (c + 3) * BK8);
            CP_COMMIT;
        }

        const float* a_s = sA[c & 3];
        const float* b_s = sB[c & 3];
        uint32_t afr[4][4], bfr[4][2];
        #pragma unroll
        for (int mt = 0; mt < 4; mt++) {
            const float* ap = a_s + (wm + mt * 16 + lm) * P12 + lk;
            afr[mt][0] = f2tf32(ap[0]);
            afr[mt][1] = f2tf32(ap[8 * P12]);
            afr[mt][2] = f2tf32(ap[4]);
            afr[mt][3] = f2tf32(ap[8 * P12 + 4]);
        }
        #pragma unroll
        for (int nt = 0; nt < 4; nt++) {
            const float* bp = b_s + (wn + nt * 8 + lm) * P12 + lk;
            bfr[nt][0] = f2tf32(bp[0]);
            bfr[nt][1] = f2tf32(bp[4]);
        }
        #pragma unroll
        for (int mt = 0; mt < 4; mt++)
            #pragma unroll
            for (int nt = 0; nt < 4; nt++)
                MMA_TF32(acc[mt][nt], afr[mt], bfr[nt]);
    }

    // Epilogue
    #pragma unroll
    for (int mt = 0; mt < 4; mt++) {
        const int r0 = m0 + wm + mt * 16 + lm;
        const int r1 = r0 + 8;
        float rs0 = 1.0f, rs1 = 1.0f;
        if (rowscale) { rs0 = rowscale[r0]; rs1 = rowscale[r1]; }
        #pragma unroll
        for (int nt = 0; nt < 4; nt++) {
            const int col = n0 + wn + nt * 8 + lk * 2;
            float2 bb = *(const float2*)&bias[col];
            float v0 = acc[mt][nt][0] * rs0 + bb.x;
            float v1 = acc[mt][nt][1] * rs0 + bb.y;
            float v2 = acc[mt][nt][2] * rs1 + bb.x;
            float v3 = acc[mt][nt][3] * rs1 + bb.y;
            if (EPI == 1) {
                v0 = fmaxf(v0, 0.0f);
                v1 = fmaxf(v1, 0.0f);
                v2 = fmaxf(v2, 0.0f);
                v3 = fmaxf(v3, 0.0f);
            }
            if (EPI == 2) {
                float2 q0 = *(const float2*)&res[(size_t)r0 * Ndim + col];
                float2 q1 = *(const float2*)&res[(size_t)r1 * Ndim + col];
                v0 += q0.x; v1 += q0.y; v2 += q1.x; v3 += q1.y;
            }
            *(float2*)&C[(size_t)r0 * Ndim + col] = make_float2(v0, v1);
            *(float2*)&C[(size_t)r1 * Ndim + col] = make_float2(v2, v3);
        }
    }
}

// ---------------------------------------------------------------------------
// Tensor-core flash attention (tf32 mma.sync). Unchanged from R9-passing.
// ---------------------------------------------------------------------------
__global__ void __launch_bounds__(128)
attn_tc_kernel(const float* __restrict__ q, const float* __restrict__ k,
               const float* __restrict__ v, float* __restrict__ ctx) {
    __shared__ float sK[64 * KPITCH];    // K tile [s][d]; Q staged here first
    __shared__ float sV[64 * VPITCH];    // V tile [s][d] (natural)

    const int tid = threadIdx.x;
    const int wid = tid >> 5;
    const int lid = tid & 31;
    const int g   = lid >> 2;        // 0..7 fragment row group
    const int t   = lid & 3;         // 0..3 thread-in-quad
    const int t0  = blockIdx.x * 64;
    const int h   = blockIdx.y;
    const int b   = blockIdx.z;
    const size_t rs = (size_t)BB * EE;
    const float* qb = q + (size_t)b * EE + h * HK;
    const float* kb = k + (size_t)b * EE + h * HK;
    const float* vb = v + (size_t)b * EE + h * HK;
    float* cb = ctx + (size_t)b * EE + h * HK;

    // Stage Q (pre-scaled by 1/8 — exact power of 2 — then tf32-rounded)
    #pragma unroll
    for (int p = 0; p < 8; p++) {
        int s   = tid + p * 128;
        int row = s >> 4;
        int c4  = (s & 15) * 4;
        float4 vq = *(const float4*)&qb[(size_t)(t0 + row) * rs + c4];
        sK[row * KPITCH + c4 + 0] = f2tf32f(vq.x * 0.125f);
        sK[row * KPITCH + c4 + 1] = f2tf32f(vq.y * 0.125f);
        sK[row * KPITCH + c4 + 2] = f2tf32f(vq.z * 0.125f);
        sK[row * KPITCH + c4 + 3] = f2tf32f(vq.w * 0.125f);
    }
    __syncthreads();

    // Q fragments for rows wid*16+g, +8 (register-resident all kernel)
    uint32_t qf[8][4];
    #pragma unroll
    for (int kk = 0; kk < 8; kk++) {
        const float* ap = sK + (wid * 16 + g) * KPITCH + kk * 8 + t;
        qf[kk][0] = __float_as_uint(ap[0]);
        qf[kk][1] = __float_as_uint(ap[8 * KPITCH]);
        qf[kk][2] = __float_as_uint(ap[4]);
        qf[kk][3] = __float_as_uint(ap[8 * KPITCH + 4]);
    }

    float mx0 = -INFINITY, mx1 = -INFINITY, l0 = 0.0f, l1 = 0.0f;
    float o[8][4];
    #pragma unroll
    for (int dd = 0; dd < 8; dd++)
        #pragma unroll
        for (int r = 0; r < 4; r++) o[dd][r] = 0.0f;

    const int l0lane = (lid & 28) | (t >> 1);
    const int l2lane = l0lane | 2;
    const bool odd = t & 1;

    for (int s0 = 0; s0 < TT; s0 += 64) {
        __syncthreads();   // previous tile reads done (covers Q-frag reads too)
        // Stage K [s][d] and V [s][d], tf32-rounded
        #pragma unroll
        for (int p = 0; p < 8; p++) {
            int s   = tid + p * 128;
            int row = s >> 4;
            int c4  = (s & 15) * 4;
            float4 kv = *(const float4*)&kb[(size_t)(s0 + row) * rs + c4];
            sK[row * KPITCH + c4 + 0] = f2tf32f(kv.x);
            sK[row * KPITCH + c4 + 1] = f2tf32f(kv.y);
            sK[row * KPITCH + c4 + 2] = f2tf32f(kv.z);
            sK[row * KPITCH + c4 + 3] = f2tf32f(kv.w);
            float4 vv = *(const float4*)&vb[(size_t)(s0 + row) * rs + c4];
            sV[row * VPITCH + c4 + 0] = f2tf32f(vv.x);
            sV[row * VPITCH + c4 + 1] = f2tf32f(vv.y);
            sV[row * VPITCH + c4 + 2] = f2tf32f(vv.z);
            sV[row * VPITCH + c4 + 3] = f2tf32f(vv.w);
        }
        __syncthreads();

        // S = Q K^T (m16 x n64 per warp)
        float sc[8][4];
        #pragma unroll
        for (int nt = 0; nt < 8; nt++) {
            float c[4] = {0.0f, 0.0f, 0.0f, 0.0f};
            #pragma unroll
            for (int kk = 0; kk < 8; kk++) {
                const float* bp = sK + (nt * 8 + g) * KPITCH + kk * 8 + t;
                uint32_t bf[2] = {__float_as_uint(bp[0]), __float_as_uint(bp[4])};
                MMA_TF32(c, qf[kk], bf);
            }
            sc[nt][0] = c[0]; sc[nt][1] = c[1]; sc[nt][2] = c[2]; sc[nt][3] = c[3];
        }

        // Online softmax (rows g, g+8)
        float rmax0 = -INFINITY, rmax1 = -INFINITY;
        #pragma unroll
        for (int nt = 0; nt < 8; nt++) {
            rmax0 = fmaxf(rmax0, fmaxf(sc[nt][0], sc[nt][1]));
            rmax1 = fmaxf(rmax1, fmaxf(sc[nt][2], sc[nt][3]));
        }
        rmax0 = fmaxf(rmax0, __shfl_xor_sync(0xffffffffu, rmax0, 1));
        rmax0 = fmaxf(rmax0, __shfl_xor_sync(0xffffffffu, rmax0, 2));
        rmax1 = fmaxf(rmax1, __shfl_xor_sync(0xffffffffu, rmax1, 1));
        rmax1 = fmaxf(rmax1, __shfl_xor_sync(0xffffffffu, rmax1, 2));
        float mn0 = fmaxf(mx0, rmax0), mn1 = fmaxf(mx1, rmax1);
        float corr0 = __expf(mx0 - mn0), corr1 = __expf(mx1 - mn1);
        mx0 = mn0; mx1 = mn1;
        float s0sum = 0.0f, s1sum = 0.0f;
        #pragma unroll
        for (int nt = 0; nt < 8; nt++) {
            sc[nt][0] = __expf(sc[nt][0] - mn0);
            sc[nt][1] = __expf(sc[nt][1] - mn0);
            sc[nt][2] = __expf(sc[nt][2] - mn1);
            sc[nt][3] = __expf(sc[nt][3] - mn1);
            s0sum += sc[nt][0] + sc[nt][1];
            s1sum += sc[nt][2] + sc[nt][3];
        }
        s0sum += __shfl_xor_sync(0xffffffffu, s0sum, 1);
        s0sum += __shfl_xor_sync(0xffffffffu, s0sum, 2);
        s1sum += __shfl_xor_sync(0xffffffffu, s1sum, 1);
        s1sum += __shfl_xor_sync(0xffffffffu, s1sum, 2);
        l0 = l0 * corr0 + s0sum;
        l1 = l1 * corr1 + s1sum;
        #pragma unroll
        for (int dd = 0; dd < 8; dd++) {
            o[dd][0] *= corr0; o[dd][1] *= corr0;
            o[dd][2] *= corr1; o[dd][3] *= corr1;
        }

        // O += P V: re-fragment P via quad shuffles, read V naturally
        #pragma unroll
        for (int kk = 0; kk < 8; kk++) {
            float p0 = sc[kk][0], p1 = sc[kk][1], p2 = sc[kk][2], p3 = sc[kk][3];
            float x00 = __shfl_sync(0xffffffffu, p0, l0lane);
            float x01 = __shfl_sync(0xffffffffu, p1, l0lane);
            float x02 = __shfl_sync(0xffffffffu, p2, l0lane);
            float x03 = __shfl_sync(0xffffffffu, p3, l0lane);
            float x20 = __shfl_sync(0xffffffffu, p0, l2lane);
            float x21 = __shfl_sync(0xffffffffu, p1, l2lane);
            float x22 = __shfl_sync(0xffffffffu, p2, l2lane);
            float x23 = __shfl_sync(0xffffffffu, p3, l2lane);
            uint32_t af[4];
            af[0] = f2tf32(odd ? x01 : x00);
            af[1] = f2tf32(odd ? x03 : x02);
            af[2] = f2tf32(odd ? x21 : x20);
            af[3] = f2tf32(odd ? x23 : x22);
            const float* vrow0 = sV + (kk * 8 + t) * VPITCH;
            const float* vrow1 = sV + (kk * 8 + t + 4) * VPITCH;
            #pragma unroll
            for (int dd = 0; dd < 8; dd++) {
                uint32_t bf[2] = {__float_as_uint(vrow0[dd * 8 + g]),
                                  __float_as_uint(vrow1[dd * 8 + g])};
                MMA_TF32(o[dd], af, bf);
            }
        }
    }

    // Finalize: ctx = O / l (raw f32; Wo GEMM rounds on load)
    const float inv0 = 1.0f / l0, inv1 = 1.0f / l1;
    const int row0 = t0 + wid * 16 + g;
    const int row1 = row0 + 8;
    #pragma unroll
    for (int dd = 0; dd < 8; dd++) {
        const int col = dd * 8 + t * 2;
        *(float2*)&cb[(size_t)row0 * rs + col] =
            make_float2(o[dd][0] * inv0, o[dd][1] * inv0);
        *(float2*)&cb[(size_t)row1 * rs + col] =
            make_float2(o[dd][2] * inv1, o[dd][3] * inv1);
    }
}

// ---------------------------------------------------------------------------
// LayerNorm over E=1024, one block (256 threads) per row.
// ---------------------------------------------------------------------------
__device__ __forceinline__ float block_reduce_sum(float v) {
    #pragma unroll
    for (int o = 16; o > 0; o >>= 1) v += __shfl_xor_sync(0xffffffffu, v, o);
    __shared__ float red[8];
    __shared__ float tot;
    int w = threadIdx.x >> 5;
    if ((threadIdx.x & 31) == 0) red[w] = v;
    __syncthreads();
    if (threadIdx.x == 0) {
        float t = 0.0f;
        #pragma unroll
        for (int i = 0; i < 8; i++) t += red[i];
        tot = t;
    }
    __syncthreads();
    return tot;
}

__global__ void __launch_bounds__(256)
ln_kernel(const float* __restrict__ x, const float* __restrict__ gamma,
          const float* __restrict__ beta, float* __restrict__ y) {
    const int row = blockIdx.x;
    const int tid = threadIdx.x;
    float4 v = *(const float4*)&x[(size_t)row * EE + tid * 4];
    float s = v.x + v.y + v.z + v.w;
    float mu = block_reduce_sum(s) * (1.0f / EE);
    float dx = v.x - mu, dy = v.y - mu, dz = v.z - mu, dw = v.w - mu;
    float sq = dx * dx + dy * dy + dz * dz + dw * dw;
    float var = block_reduce_sum(sq) * (1.0f / EE);
    float rstd = rsqrtf(var + LN_EPS);
    float4 g = *(const float4*)&gamma[tid * 4];
    float4 b = *(const float4*)&beta[tid * 4];
    float4 o;
    o.x = dx * rstd * g.x + b.x;
    o.y = dy * rstd * g.y + b.y;
    o.z = dz * rstd * g.z + b.z;
    o.w = dw * rstd * g.w + b.w;
    *(float4*)&y[(size_t)row * EE + tid * 4] = o;
}

// ---------------------------------------------------------------------------
// Launch
// ---------------------------------------------------------------------------
extern "C" void kernel_launch(void* const* d_in, const int* in_sizes, int n_in,
                              void* d_out, int out_size) {
    (void)in_sizes; (void)n_in; (void)out_size;
    const float* state = (const float*)d_in[0];
    const void*  mask  = d_in[1];
    const float* Wq = (const float*)d_in[2];
    const float* bq = (const float*)d_in[3];
    const float* Wk = (const float*)d_in[4];
    const float* bk = (const float*)d_in[5];
    const float* Wv = (const float*)d_in[6];
    const float* bv = (const float*)d_in[7];
    const float* Wo = (const float*)d_in[8];
    const float* bo = (const float*)d_in[9];
    const float* ln1g = (const float*)d_in[10];
    const float* ln1b = (const float*)d_in[11];
    const float* W1 = (const float*)d_in[12];
    const float* b1 = (const float*)d_in[13];
    const float* W2 = (const float*)d_in[14];
    const float* b2 = (const float*)d_in[15];
    const float* ln2g = (const float*)d_in[16];
    const float* ln2b = (const float*)d_in[17];
    float* out = (float*)d_out;

    float *qp, *kp, *vp, *cp, *t1, *s1, *hd, *t2, *keep;
    cudaGetSymbolAddress((void**)&qp,   g_q);
    cudaGetSymbolAddress((void**)&kp,   g_k);
    cudaGetSymbolAddress((void**)&vp,   g_v);
    cudaGetSymbolAddress((void**)&cp,   g_ctx);
    cudaGetSymbolAddress((void**)&t1,   g_t1);
    cudaGetSymbolAddress((void**)&s1,   g_s1);
    cudaGetSymbolAddress((void**)&hd,   g_hid);
    cudaGetSymbolAddress((void**)&t2,   g_t2);
    cudaGetSymbolAddress((void**)&keep, g_keep);

    detect_mask_kernel<<<1, 256>>>((const unsigned char*)mask);
    build_keep_kernel<<<MM / 256, 256>>>(mask);

    dim3 gE(EE / 128, MM / 128);     // (8, 32)
    dim3 gF(FFD / 128, MM / 128);    // (32, 32)

    // Projections (key mask as epilogue rowscale on K projection)
    gemm_mma_kernel<0><<<gE, 256>>>(state, Wq, bq, nullptr, nullptr, qp, EE, EE);
    gemm_mma_kernel<0><<<gE, 256>>>(state, Wk, bk, keep,    nullptr, kp, EE, EE);
    gemm_mma_kernel<0><<<gE, 256>>>(state, Wv, bv, nullptr, nullptr, vp, EE, EE);

    // Attention (tensor-core flash)
    attn_tc_kernel<<<dim3(TT / 64, HH, BB), 128>>>(qp, kp, vp, cp);

    // O projection + residual, LN1
    gemm_mma_kernel<2><<<gE, 256>>>(cp, Wo, bo, nullptr, state, t1, EE, EE);
    ln_kernel<<<MM, 256>>>(t1, ln1g, ln1b, s1);

    // FFN
    gemm_mma_kernel<1><<<gF, 256>>>(s1, W1, b1, nullptr, nullptr, hd, FFD, EE);
    gemm_mma_kernel<2><<<gE, 256>>>(hd, W2, b2, nullptr, s1, t2, EE, FFD);

    // LN2 -> output
    ln_kernel<<<MM, 256>>>(t2, ln2g, ln2b, out);
}

// round 12
// speedup vs baseline: 1.2991x; 1.2991x over previous
#include <cuda_runtime.h>
#include <cuda_bf16.h>
#include <cstdint>
#include <cstddef>

// Problem constants
#define TT 2048
#define BB 2
#define EE 1024
#define HH 16
#define HK 64          // head dim
#define FFD 4096
#define MM (TT*BB)     // 4096 rows
#define LN_EPS 1e-5f
#define BKC 16         // GEMM K chunk
#define SPITCH 20      // smem row pitch in floats (16 data + 4 pad)
#define KPITCH 68      // attention K-tile pitch
#define VPITCH 72      // attention V-tile pitch

// ---------------------------------------------------------------------------
// Scratch (device globals; no allocation allowed)
// ---------------------------------------------------------------------------
__device__ float g_keep[MM];
__device__ int   g_maskmode;
__device__ float g_q[MM * EE];
__device__ float g_k[MM * EE];
__device__ float g_v[MM * EE];
__device__ float g_ctx[MM * EE];
__device__ float g_t1[MM * EE];
__device__ float g_s1[MM * EE];      // LN1 out (residual + FFN1 A)
__device__ float g_hid[(size_t)MM * FFD];
__device__ float g_t2[MM * EE];

// ---------------------------------------------------------------------------
// Helpers
// ---------------------------------------------------------------------------
__device__ __forceinline__ uint32_t smem_u32(const void* p) {
    uint32_t a;
    asm("{ .reg .u64 t; cvta.to.shared.u64 t, %1; cvt.u32.u64 %0, t; }"
        : "=r"(a) : "l"(p));
    return a;
}

__device__ __forceinline__ uint32_t f2tf32(float x) {
    uint32_t r;
    asm("cvt.rna.tf32.f32 %0, %1;" : "=r"(r) : "f"(x));
    return r;
}
__device__ __forceinline__ float f2tf32f(float x) {
    return __uint_as_float(f2tf32(x));
}

#define CP_ASYNC16(dst_u32, src_ptr) \
    asm volatile("cp.async.cg.shared.global [%0], [%1], 16;" \
                 :: "r"(dst_u32), "l"(src_ptr) : "memory")
#define CP_COMMIT asm volatile("cp.async.commit_group;" ::: "memory")
#define CP_WAIT0  asm volatile("cp.async.wait_group 0;" ::: "memory")

#define MMA_TF32(c, a, b) \
    asm volatile("mma.sync.aligned.m16n8k8.row.col.f32.tf32.tf32.f32 " \
        "{%0,%1,%2,%3}, {%4,%5,%6,%7}, {%8,%9}, {%0,%1,%2,%3};" \
        : "+f"((c)[0]), "+f"((c)[1]), "+f"((c)[2]), "+f"((c)[3]) \
        : "r"((a)[0]), "r"((a)[1]), "r"((a)[2]), "r"((a)[3]), \
          "r"((b)[0]), "r"((b)[1]))

// ---------------------------------------------------------------------------
// Mask dtype detection + keep vector
// ---------------------------------------------------------------------------
__global__ void detect_mask_kernel(const unsigned char* __restrict__ mask) {
    __shared__ int cnt[4];
    if (threadIdx.x < 4) cnt[threadIdx.x] = 0;
    __syncthreads();
    for (int i = threadIdx.x; i < BB * TT; i += blockDim.x) {
        if (mask[i]) atomicAdd(&cnt[i & 3], 1);
    }
    __syncthreads();
    if (threadIdx.x == 0) {
        int mode;
        if (cnt[1] > 0)                    mode = 0;  // bytes
        else if (cnt[2] > 0 || cnt[3] > 0) mode = 2;  // float32
        else if (cnt[0] > 0)               mode = 1;  // int32
        else                               mode = 3;  // all zero
        g_maskmode = mode;
    }
}

__global__ void build_keep_kernel(const void* __restrict__ mask) {
    int m = blockIdx.x * blockDim.x + threadIdx.x;
    if (m >= MM) return;
    int t = m >> 1;
    int b = m & 1;
    int idx = b * TT + t;
    int mode = g_maskmode;
    bool pad;
    if (mode == 0)      pad = ((const unsigned char*)mask)[idx] != 0;
    else if (mode == 1) pad = ((const int*)mask)[idx] != 0;
    else if (mode == 2) pad = ((const float*)mask)[idx] != 0.0f;
    else                pad = false;
    g_keep[m] = pad ? 0.0f : 1.0f;
}

// ---------------------------------------------------------------------------
// tf32 mma.sync NT GEMM:  C[M,N] = epi( rowscale[m]*(A[M,K]*B[N,K]^T) + bias[N] )
//   EPI 0: + bias; EPI 1: + bias, ReLU; EPI 2: + bias + residual
// R9-proven geometry: CTA tile 128x128, BK=16, 8 warps (2Mx4N), warp 64x32,
// m16n8k8, cp.async double-buffered, pitch-20 smem (conflict-free).
// Single-barrier mainloop — wait(c) -> sync -> issue(c+1) -> compute(c).
// The sync both publishes chunk c and proves compute(c-1) done (buffer free).
// Fragments rounded to tf32 (rna) after LDS — bit-identical to pre-rounding.
// ---------------------------------------------------------------------------
template <int EPI>
__global__ void __launch_bounds__(256, 2)
gemm_mma_kernel(const float* __restrict__ A, const float* __restrict__ Bw,
                const float* __restrict__ bias, const float* __restrict__ rowscale,
                const float* __restrict__ res, float* __restrict__ C,
                int Ndim, int Kdim) {
    __shared__ __align__(16) float sA[2][128 * SPITCH];
    __shared__ __align__(16) float sB[2][128 * SPITCH];

    const int tid = threadIdx.x;
    const int wid = tid >> 5;
    const int lid = tid & 31;
    const int m0 = blockIdx.y * 128;
    const int n0 = blockIdx.x * 128;
    const int wm = (wid >> 2) * 64;   // warp M offset
    const int wn = (wid & 3) * 32;    // warp N offset
    const int lm = lid >> 2;          // 0..7
    const int lk = lid & 3;           // 0..3

    // Staging geometry: thread covers rows srow, srow+64; 16B k-group sq.
    const int srow = tid >> 2;        // 0..63
    const int sq   = (tid & 3) * 4;   // 0,4,8,12 floats
    const float* Ag0 = A  + (size_t)(m0 + srow)      * Kdim + sq;
    const float* Ag1 = A  + (size_t)(m0 + srow + 64) * Kdim + sq;
    const float* Bg0 = Bw + (size_t)(n0 + srow)      * Kdim + sq;
    const float* Bg1 = Bw + (size_t)(n0 + srow + 64) * Kdim + sq;
    const uint32_t sa0 = smem_u32(&sA[0][srow * SPITCH + sq]);
    const uint32_t sa1 = smem_u32(&sA[0][(srow + 64) * SPITCH + sq]);
    const uint32_t sb0 = smem_u32(&sB[0][srow * SPITCH + sq]);
    const uint32_t sb1 = smem_u32(&sB[0][(srow + 64) * SPITCH + sq]);
    const uint32_t bufB = 128 * SPITCH * 4;   // bytes per buffer

    float acc[4][4][4];
    #pragma unroll
    for (int mt = 0; mt < 4; mt++)
        #pragma unroll
        for (int nt = 0; nt < 4; nt++)
            #pragma unroll
            for (int r = 0; r < 4; r++) acc[mt][nt][r] = 0.0f;

    const int nch = Kdim / BKC;

    // prologue: stage chunk 0 into buffer 0
    {
        CP_ASYNC16(sa0, Ag0); CP_ASYNC16(sa1, Ag1);
        CP_ASYNC16(sb0, Bg0); CP_ASYNC16(sb1, Bg1);
        CP_COMMIT;
    }

    for (int c = 0; c < nch; c++) {
        CP_WAIT0;                 // chunk c complete (this thread's group)
        __syncthreads();          // publish chunk c; compute(c-1) done by all
        if (c + 1 < nch) {        // stage chunk c+1 into the freed buffer
            const int koff = (c + 1) * BKC;
            const uint32_t bs = ((c + 1) & 1) * bufB;
            CP_ASYNC16(sa0 + bs, Ag0 + koff);
            CP_ASYNC16(sa1 + bs, Ag1 + koff);
            CP_ASYNC16(sb0 + bs, Bg0 + koff);
            CP_ASYNC16(sb1 + bs, Bg1 + koff);
            CP_COMMIT;
        }

        const float* a_s = sA[c & 1];
        const float* b_s = sB[c & 1];
        #pragma unroll
        for (int ks = 0; ks < 2; ks++) {
            const int k0 = ks * 8;
            uint32_t afr[4][4], bfr[4][2];
            #pragma unroll
            for (int mt = 0; mt < 4; mt++) {
                const float* ap = a_s + (wm + mt * 16 + lm) * SPITCH + k0 + lk;
                afr[mt][0] = f2tf32(ap[0]);
                afr[mt][1] = f2tf32(ap[8 * SPITCH]);
                afr[mt][2] = f2tf32(ap[4]);
                afr[mt][3] = f2tf32(ap[8 * SPITCH + 4]);
            }
            #pragma unroll
            for (int nt = 0; nt < 4; nt++) {
                const float* bp = b_s + (wn + nt * 8 + lm) * SPITCH + k0 + lk;
                bfr[nt][0] = f2tf32(bp[0]);
                bfr[nt][1] = f2tf32(bp[4]);
            }
            #pragma unroll
            for (int mt = 0; mt < 4; mt++)
                #pragma unroll
                for (int nt = 0; nt < 4; nt++)
                    MMA_TF32(acc[mt][nt], afr[mt], bfr[nt]);
        }
    }

    // Epilogue
    #pragma unroll
    for (int mt = 0; mt < 4; mt++) {
        const int r0 = m0 + wm + mt * 16 + lm;
        const int r1 = r0 + 8;
        float rs0 = 1.0f, rs1 = 1.0f;
        if (rowscale) { rs0 = rowscale[r0]; rs1 = rowscale[r1]; }
        #pragma unroll
        for (int nt = 0; nt < 4; nt++) {
            const int col = n0 + wn + nt * 8 + lk * 2;
            float2 bb = *(const float2*)&bias[col];
            float v0 = acc[mt][nt][0] * rs0 + bb.x;
            float v1 = acc[mt][nt][1] * rs0 + bb.y;
            float v2 = acc[mt][nt][2] * rs1 + bb.x;
            float v3 = acc[mt][nt][3] * rs1 + bb.y;
            if (EPI == 1) {
                v0 = fmaxf(v0, 0.0f);
                v1 = fmaxf(v1, 0.0f);
                v2 = fmaxf(v2, 0.0f);
                v3 = fmaxf(v3, 0.0f);
            }
            if (EPI == 2) {
                float2 q0 = *(const float2*)&res[(size_t)r0 * Ndim + col];
                float2 q1 = *(const float2*)&res[(size_t)r1 * Ndim + col];
                v0 += q0.x; v1 += q0.y; v2 += q1.x; v3 += q1.y;
            }
            *(float2*)&C[(size_t)r0 * Ndim + col] = make_float2(v0, v1);
            *(float2*)&C[(size_t)r1 * Ndim + col] = make_float2(v2, v3);
        }
    }
}

// ---------------------------------------------------------------------------
// Tensor-core flash attention (tf32 mma.sync). Unchanged from R9-passing.
// ---------------------------------------------------------------------------
__global__ void __launch_bounds__(128)
attn_tc_kernel(const float* __restrict__ q, const float* __restrict__ k,
               const float* __restrict__ v, float* __restrict__ ctx) {
    __shared__ float sK[64 * KPITCH];    // K tile [s][d]; Q staged here first
    __shared__ float sV[64 * VPITCH];    // V tile [s][d] (natural)

    const int tid = threadIdx.x;
    const int wid = tid >> 5;
    const int lid = tid & 31;
    const int g   = lid >> 2;        // 0..7 fragment row group
    const int t   = lid & 3;         // 0..3 thread-in-quad
    const int t0  = blockIdx.x * 64;
    const int h   = blockIdx.y;
    const int b   = blockIdx.z;
    const size_t rs = (size_t)BB * EE;
    const float* qb = q + (size_t)b * EE + h * HK;
    const float* kb = k + (size_t)b * EE + h * HK;
    const float* vb = v + (size_t)b * EE + h * HK;
    float* cb = ctx + (size_t)b * EE + h * HK;

    // Stage Q (pre-scaled by 1/8 — exact power of 2 — then tf32-rounded)
    #pragma unroll
    for (int p = 0; p < 8; p++) {
        int s   = tid + p * 128;
        int row = s >> 4;
        int c4  = (s & 15) * 4;
        float4 vq = *(const float4*)&qb[(size_t)(t0 + row) * rs + c4];
        sK[row * KPITCH + c4 + 0] = f2tf32f(vq.x * 0.125f);
        sK[row * KPITCH + c4 + 1] = f2tf32f(vq.y * 0.125f);
        sK[row * KPITCH + c4 + 2] = f2tf32f(vq.z * 0.125f);
        sK[row * KPITCH + c4 + 3] = f2tf32f(vq.w * 0.125f);
    }
    __syncthreads();

    // Q fragments for rows wid*16+g, +8 (register-resident all kernel)
    uint32_t qf[8][4];
    #pragma unroll
    for (int kk = 0; kk < 8; kk++) {
        const float* ap = sK + (wid * 16 + g) * KPITCH + kk * 8 + t;
        qf[kk][0] = __float_as_uint(ap[0]);
        qf[kk][1] = __float_as_uint(ap[8 * KPITCH]);
        qf[kk][2] = __float_as_uint(ap[4]);
        qf[kk][3] = __float_as_uint(ap[8 * KPITCH + 4]);
    }

    float mx0 = -INFINITY, mx1 = -INFINITY, l0 = 0.0f, l1 = 0.0f;
    float o[8][4];
    #pragma unroll
    for (int dd = 0; dd < 8; dd++)
        #pragma unroll
        for (int r = 0; r < 4; r++) o[dd][r] = 0.0f;

    const int l0lane = (lid & 28) | (t >> 1);
    const int l2lane = l0lane | 2;
    const bool odd = t & 1;

    for (int s0 = 0; s0 < TT; s0 += 64) {
        __syncthreads();   // previous tile reads done (covers Q-frag reads too)
        // Stage K [s][d] and V [s][d], tf32-rounded
        #pragma unroll
        for (int p = 0; p < 8; p++) {
            int s   = tid + p * 128;
            int row = s >> 4;
            int c4  = (s & 15) * 4;
            float4 kv = *(const float4*)&kb[(size_t)(s0 + row) * rs + c4];
            sK[row * KPITCH + c4 + 0] = f2tf32f(kv.x);
            sK[row * KPITCH + c4 + 1] = f2tf32f(kv.y);
            sK[row * KPITCH + c4 + 2] = f2tf32f(kv.z);
            sK[row * KPITCH + c4 + 3] = f2tf32f(kv.w);
            float4 vv = *(const float4*)&vb[(size_t)(s0 + row) * rs + c4];
            sV[row * VPITCH + c4 + 0] = f2tf32f(vv.x);
            sV[row * VPITCH + c4 + 1] = f2tf32f(vv.y);
            sV[row * VPITCH + c4 + 2] = f2tf32f(vv.z);
            sV[row * VPITCH + c4 + 3] = f2tf32f(vv.w);
        }
        __syncthreads();

        // S = Q K^T (m16 x n64 per warp)
        float sc[8][4];
        #pragma unroll
        for (int nt = 0; nt < 8; nt++) {
            float c[4] = {0.0f, 0.0f, 0.0f, 0.0f};
            #pragma unroll
            for (int kk = 0; kk < 8; kk++) {
                const float* bp = sK + (nt * 8 + g) * KPITCH + kk * 8 + t;
                uint32_t bf[2] = {__float_as_uint(bp[0]), __float_as_uint(bp[4])};
                MMA_TF32(c, qf[kk], bf);
            }
            sc[nt][0] = c[0]; sc[nt][1] = c[1]; sc[nt][2] = c[2]; sc[nt][3] = c[3];
        }

        // Online softmax (rows g, g+8)
        float rmax0 = -INFINITY, rmax1 = -INFINITY;
        #pragma unroll
        for (int nt = 0; nt < 8; nt++) {
            rmax0 = fmaxf(rmax0, fmaxf(sc[nt][0], sc[nt][1]));
            rmax1 = fmaxf(rmax1, fmaxf(sc[nt][2], sc[nt][3]));
        }
        rmax0 = fmaxf(rmax0, __shfl_xor_sync(0xffffffffu, rmax0, 1));
        rmax0 = fmaxf(rmax0, __shfl_xor_sync(0xffffffffu, rmax0, 2));
        rmax1 = fmaxf(rmax1, __shfl_xor_sync(0xffffffffu, rmax1, 1));
        rmax1 = fmaxf(rmax1, __shfl_xor_sync(0xffffffffu, rmax1, 2));
        float mn0 = fmaxf(mx0, rmax0), mn1 = fmaxf(mx1, rmax1);
        float corr0 = __expf(mx0 - mn0), corr1 = __expf(mx1 - mn1);
        mx0 = mn0; mx1 = mn1;
        float s0sum = 0.0f, s1sum = 0.0f;
        #pragma unroll
        for (int nt = 0; nt < 8; nt++) {
            sc[nt][0] = __expf(sc[nt][0] - mn0);
            sc[nt][1] = __expf(sc[nt][1] - mn0);
            sc[nt][2] = __expf(sc[nt][2] - mn1);
            sc[nt][3] = __expf(sc[nt][3] - mn1);
            s0sum += sc[nt][0] + sc[nt][1];
            s1sum += sc[nt][2] + sc[nt][3];
        }
        s0sum += __shfl_xor_sync(0xffffffffu, s0sum, 1);
        s0sum += __shfl_xor_sync(0xffffffffu, s0sum, 2);
        s1sum += __shfl_xor_sync(0xffffffffu, s1sum, 1);
        s1sum += __shfl_xor_sync(0xffffffffu, s1sum, 2);
        l0 = l0 * corr0 + s0sum;
        l1 = l1 * corr1 + s1sum;
        #pragma unroll
        for (int dd = 0; dd < 8; dd++) {
            o[dd][0] *= corr0; o[dd][1] *= corr0;
            o[dd][2] *= corr1; o[dd][3] *= corr1;
        }

        // O += P V: re-fragment P via quad shuffles, read V naturally
        #pragma unroll
        for (int kk = 0; kk < 8; kk++) {
            float p0 = sc[kk][0], p1 = sc[kk][1], p2 = sc[kk][2], p3 = sc[kk][3];
            float x00 = __shfl_sync(0xffffffffu, p0, l0lane);
            float x01 = __shfl_sync(0xffffffffu, p1, l0lane);
            float x02 = __shfl_sync(0xffffffffu, p2, l0lane);
            float x03 = __shfl_sync(0xffffffffu, p3, l0lane);
            float x20 = __shfl_sync(0xffffffffu, p0, l2lane);
            float x21 = __shfl_sync(0xffffffffu, p1, l2lane);
            float x22 = __shfl_sync(0xffffffffu, p2, l2lane);
            float x23 = __shfl_sync(0xffffffffu, p3, l2lane);
            uint32_t af[4];
            af[0] = f2tf32(odd ? x01 : x00);
            af[1] = f2tf32(odd ? x03 : x02);
            af[2] = f2tf32(odd ? x21 : x20);
            af[3] = f2tf32(odd ? x23 : x22);
            const float* vrow0 = sV + (kk * 8 + t) * VPITCH;
            const float* vrow1 = sV + (kk * 8 + t + 4) * VPITCH;
            #pragma unroll
            for (int dd = 0; dd < 8; dd++) {
                uint32_t bf[2] = {__float_as_uint(vrow0[dd * 8 + g]),
                                  __float_as_uint(vrow1[dd * 8 + g])};
                MMA_TF32(o[dd], af, bf);
            }
        }
    }

    // Finalize: ctx = O / l (raw f32; Wo GEMM rounds on load)
    const float inv0 = 1.0f / l0, inv1 = 1.0f / l1;
    const int row0 = t0 + wid * 16 + g;
    const int row1 = row0 + 8;
    #pragma unroll
    for (int dd = 0; dd < 8; dd++) {
        const int col = dd * 8 + t * 2;
        *(float2*)&cb[(size_t)row0 * rs + col] =
            make_float2(o[dd][0] * inv0, o[dd][1] * inv0);
        *(float2*)&cb[(size_t)row1 * rs + col] =
            make_float2(o[dd][2] * inv1, o[dd][3] * inv1);
    }
}

// ---------------------------------------------------------------------------
// LayerNorm over E=1024, one block (256 threads) per row.
// ---------------------------------------------------------------------------
__device__ __forceinline__ float block_reduce_sum(float v) {
    #pragma unroll
    for (int o = 16; o > 0; o >>= 1) v += __shfl_xor_sync(0xffffffffu, v, o);
    __shared__ float red[8];
    __shared__ float tot;
    int w = threadIdx.x >> 5;
    if ((threadIdx.x & 31) == 0) red[w] = v;
    __syncthreads();
    if (threadIdx.x == 0) {
        float t = 0.0f;
        #pragma unroll
        for (int i = 0; i < 8; i++) t += red[i];
        tot = t;
    }
    __syncthreads();
    return tot;
}

__global__ void __launch_bounds__(256)
ln_kernel(const float* __restrict__ x, const float* __restrict__ gamma,
          const float* __restrict__ beta, float* __restrict__ y) {
    const int row = blockIdx.x;
    const int tid = threadIdx.x;
    float4 v = *(const float4*)&x[(size_t)row * EE + tid * 4];
    float s = v.x + v.y + v.z + v.w;
    float mu = block_reduce_sum(s) * (1.0f / EE);
    float dx = v.x - mu, dy = v.y - mu, dz = v.z - mu, dw = v.w - mu;
    float sq = dx * dx + dy * dy + dz * dz + dw * dw;
    float var = block_reduce_sum(sq) * (1.0f / EE);
    float rstd = rsqrtf(var + LN_EPS);
    float4 g = *(const float4*)&gamma[tid * 4];
    float4 b = *(const float4*)&beta[tid * 4];
    float4 o;
    o.x = dx * rstd * g.x + b.x;
    o.y = dy * rstd * g.y + b.y;
    o.z = dz * rstd * g.z + b.z;
    o.w = dw * rstd * g.w + b.w;
    *(float4*)&y[(size_t)row * EE + tid * 4] = o;
}

// ---------------------------------------------------------------------------
// Launch
// ---------------------------------------------------------------------------
extern "C" void kernel_launch(void* const* d_in, const int* in_sizes, int n_in,
                              void* d_out, int out_size) {
    (void)in_sizes; (void)n_in; (void)out_size;
    const float* state = (const float*)d_in[0];
    const void*  mask  = d_in[1];
    const float* Wq = (const float*)d_in[2];
    const float* bq = (const float*)d_in[3];
    const float* Wk = (const float*)d_in[4];
    const float* bk = (const float*)d_in[5];
    const float* Wv = (const float*)d_in[6];
    const float* bv = (const float*)d_in[7];
    const float* Wo = (const float*)d_in[8];
    const float* bo = (const float*)d_in[9];
    const float* ln1g = (const float*)d_in[10];
    const float* ln1b = (const float*)d_in[11];
    const float* W1 = (const float*)d_in[12];
    const float* b1 = (const float*)d_in[13];
    const float* W2 = (const float*)d_in[14];
    const float* b2 = (const float*)d_in[15];
    const float* ln2g = (const float*)d_in[16];
    const float* ln2b = (const float*)d_in[17];
    float* out = (float*)d_out;

    float *qp, *kp, *vp, *cp, *t1, *s1, *hd, *t2, *keep;
    cudaGetSymbolAddress((void**)&qp,   g_q);
    cudaGetSymbolAddress((void**)&kp,   g_k);
    cudaGetSymbolAddress((void**)&vp,   g_v);
    cudaGetSymbolAddress((void**)&cp,   g_ctx);
    cudaGetSymbolAddress((void**)&t1,   g_t1);
    cudaGetSymbolAddress((void**)&s1,   g_s1);
    cudaGetSymbolAddress((void**)&hd,   g_hid);
    cudaGetSymbolAddress((void**)&t2,   g_t2);
    cudaGetSymbolAddress((void**)&keep, g_keep);

    detect_mask_kernel<<<1, 256>>>((const unsigned char*)mask);
    build_keep_kernel<<<MM / 256, 256>>>(mask);

    dim3 gE(EE / 128, MM / 128);     // (8, 32)
    dim3 gF(FFD / 128, MM / 128);    // (32, 32)

    // Projections (key mask as epilogue rowscale on K projection)
    gemm_mma_kernel<0><<<gE, 256>>>(state, Wq, bq, nullptr, nullptr, qp, EE, EE);
    gemm_mma_kernel<0><<<gE, 256>>>(state, Wk, bk, keep,    nullptr, kp, EE, EE);
    gemm_mma_kernel<0><<<gE, 256>>>(state, Wv, bv, nullptr, nullptr, vp, EE, EE);

    // Attention (tensor-core flash)
    attn_tc_kernel<<<dim3(TT / 64, HH, BB), 128>>>(qp, kp, vp, cp);

    // O projection + residual, LN1
    gemm_mma_kernel<2><<<gE, 256>>>(cp, Wo, bo, nullptr, state, t1, EE, EE);
    ln_kernel<<<MM, 256>>>(t1, ln1g, ln1b, s1);

    // FFN
    gemm_mma_kernel<1><<<gF, 256>>>(s1, W1, b1, nullptr, nullptr, hd, FFD, EE);
    gemm_mma_kernel<2><<<gE, 256>>>(hd, W2, b2, nullptr, s1, t2, EE, FFD);

    // LN2 -> output
    ln_kernel<<<MM, 256>>>(t2, ln2g, ln2b, out);
}

// round 13
// speedup vs baseline: 1.4444x; 1.1118x over previous
#include <cuda_runtime.h>
#include <cuda_bf16.h>
#include <cstdint>
#include <cstddef>

// Problem constants
#define TT 2048
#define BB 2
#define EE 1024
#define HH 16
#define HK 64          // head dim
#define FFD 4096
#define MM (TT*BB)     // 4096 rows
#define LN_EPS 1e-5f
#define BKC 16         // GEMM K chunk
#define SPITCH 20      // smem row pitch in floats (16 data + 4 pad)
#define KPITCH 68      // attention K-tile pitch
#define VPITCH 72      // attention V-tile pitch

// ---------------------------------------------------------------------------
// Scratch (device globals; no allocation allowed)
// ---------------------------------------------------------------------------
__device__ float g_keep[MM];
__device__ int   g_maskmode;
__device__ float g_q[MM * EE];
__device__ float g_k[MM * EE];
__device__ float g_v[MM * EE];
__device__ float g_ctx[MM * EE];     // tf32-rounded by attention epilogue
__device__ float g_t1[MM * EE];
__device__ float g_s1f[MM * EE];     // LN1 out, f32 (residual)
__device__ float g_s1r[MM * EE];     // LN1 out, tf32-rounded (FFN1 A)
__device__ float g_hid[(size_t)MM * FFD];  // tf32-rounded by FFN1 epilogue
__device__ float g_t2[MM * EE];
__device__ float g_rstate[MM * EE];  // tf32-rounded state
__device__ float g_rwq[EE * EE];
__device__ float g_rwk[EE * EE];
__device__ float g_rwv[EE * EE];
__device__ float g_rwo[EE * EE];
__device__ float g_rw1[(size_t)FFD * EE];
__device__ float g_rw2[(size_t)FFD * EE];

// ---------------------------------------------------------------------------
// Helpers
// ---------------------------------------------------------------------------
__device__ __forceinline__ uint32_t smem_u32(const void* p) {
    uint32_t a;
    asm("{ .reg .u64 t; cvta.to.shared.u64 t, %1; cvt.u32.u64 %0, t; }"
        : "=r"(a) : "l"(p));
    return a;
}

__device__ __forceinline__ uint32_t f2tf32(float x) {
    uint32_t r;
    asm("cvt.rna.tf32.f32 %0, %1;" : "=r"(r) : "f"(x));
    return r;
}
__device__ __forceinline__ float f2tf32f(float x) {
    return __uint_as_float(f2tf32(x));
}

#define CP_ASYNC16(dst_u32, src_ptr) \
    asm volatile("cp.async.cg.shared.global [%0], [%1], 16;" \
                 :: "r"(dst_u32), "l"(src_ptr) : "memory")
#define CP_COMMIT asm volatile("cp.async.commit_group;" ::: "memory")
#define CP_WAIT0  asm volatile("cp.async.wait_group 0;" ::: "memory")

#define MMA_TF32(c, a0, a1, a2, a3, b0, b1) \
    asm volatile("mma.sync.aligned.m16n8k8.row.col.f32.tf32.tf32.f32 " \
        "{%0,%1,%2,%3}, {%4,%5,%6,%7}, {%8,%9}, {%0,%1,%2,%3};" \
        : "+f"((c)[0]), "+f"((c)[1]), "+f"((c)[2]), "+f"((c)[3]) \
        : "r"(a0), "r"(a1), "r"(a2), "r"(a3), "r"(b0), "r"(b1))

#define LDSM_X4(r0, r1, r2, r3, addr) \
    asm volatile("ldmatrix.sync.aligned.m8n8.x4.shared.b16 {%0,%1,%2,%3}, [%4];" \
        : "=r"(r0), "=r"(r1), "=r"(r2), "=r"(r3) : "r"(addr))

// ---------------------------------------------------------------------------
// Mask dtype detection + keep vector
// ---------------------------------------------------------------------------
__global__ void detect_mask_kernel(const unsigned char* __restrict__ mask) {
    __shared__ int cnt[4];
    if (threadIdx.x < 4) cnt[threadIdx.x] = 0;
    __syncthreads();
    for (int i = threadIdx.x; i < BB * TT; i += blockDim.x) {
        if (mask[i]) atomicAdd(&cnt[i & 3], 1);
    }
    __syncthreads();
    if (threadIdx.x == 0) {
        int mode;
        if (cnt[1] > 0)                    mode = 0;  // bytes
        else if (cnt[2] > 0 || cnt[3] > 0) mode = 2;  // float32
        else if (cnt[0] > 0)               mode = 1;  // int32
        else                               mode = 3;  // all zero
        g_maskmode = mode;
    }
}

__global__ void build_keep_kernel(const void* __restrict__ mask) {
    int m = blockIdx.x * blockDim.x + threadIdx.x;
    if (m >= MM) return;
    int t = m >> 1;
    int b = m & 1;
    int idx = b * TT + t;
    int mode = g_maskmode;
    bool pad;
    if (mode == 0)      pad = ((const unsigned char*)mask)[idx] != 0;
    else if (mode == 1) pad = ((const int*)mask)[idx] != 0;
    else if (mode == 2) pad = ((const float*)mask)[idx] != 0.0f;
    else                pad = false;
    g_keep[m] = pad ? 0.0f : 1.0f;
}

// ---------------------------------------------------------------------------
// tf32 rounding pass (rna)
// ---------------------------------------------------------------------------
__global__ void round_tf32_kernel(const float* __restrict__ in,
                                  float* __restrict__ out, int n4) {
    int i = blockIdx.x * blockDim.x + threadIdx.x;
    if (i >= n4) return;
    float4 v = ((const float4*)in)[i];
    v.x = f2tf32f(v.x); v.y = f2tf32f(v.y);
    v.z = f2tf32f(v.z); v.w = f2tf32f(v.w);
    ((float4*)out)[i] = v;
}

// ---------------------------------------------------------------------------
// tf32 mma.sync NT GEMM:  C[M,N] = epi( rowscale[m]*(A[M,K]*B[N,K]^T) + bias[N] )
//   EPI 0: + bias; EPI 1: + bias, ReLU, round; EPI 2: + bias + residual
// A and B MUST be pre-rounded tf32 values (mainloop has zero cvt).
// CTA tile 128x128, BK=16, 8 warps (2Mx4N), warp 64x32, m16n8k8.
// cp.async double-buffered, pitch-20 smem, single-barrier mainloop.
// Fragment loads via ldmatrix.m8n8.x4.b16 (each "row" = 16B = 4 tf32):
// A per (mt,ks): x4 = {(r0-7,k0-3),(r8-15,k0-3),(r0-7,k4-7),(r8-15,k4-7)}
//   = exactly the tf32 A fragment {a0,a1,a2,a3}.
// B per nt: x4 = {b0ks0,b1ks0,b0ks1,b1ks1} (k groups 0,4,8,12; rows n0-7).
// Pitch-20 makes all submatrix reads bank-conflict-free (20r mod 32 perm).
// ---------------------------------------------------------------------------
template <int EPI>
__global__ void __launch_bounds__(256, 2)
gemm_mma_kernel(const float* __restrict__ A, const float* __restrict__ Bw,
                const float* __restrict__ bias, const float* __restrict__ rowscale,
                const float* __restrict__ res, float* __restrict__ C,
                int Ndim, int Kdim) {
    __shared__ __align__(16) float sA[2][128 * SPITCH];
    __shared__ __align__(16) float sB[2][128 * SPITCH];

    const int tid = threadIdx.x;
    const int wid = tid >> 5;
    const int lid = tid & 31;
    const int m0 = blockIdx.y * 128;
    const int n0 = blockIdx.x * 128;
    const int wm = (wid >> 2) * 64;   // warp M offset
    const int wn = (wid & 3) * 32;    // warp N offset
    const int lm = lid >> 2;          // 0..7
    const int lk = lid & 3;           // 0..3

    // Staging geometry: thread covers rows srow, srow+64; 16B k-group sq.
    const int srow = tid >> 2;        // 0..63
    const int sq   = (tid & 3) * 4;   // 0,4,8,12 floats
    const float* Ag0 = A  + (size_t)(m0 + srow)      * Kdim + sq;
    const float* Ag1 = A  + (size_t)(m0 + srow + 64) * Kdim + sq;
    const float* Bg0 = Bw + (size_t)(n0 + srow)      * Kdim + sq;
    const float* Bg1 = Bw + (size_t)(n0 + srow + 64) * Kdim + sq;
    const uint32_t sa0 = smem_u32(&sA[0][srow * SPITCH + sq]);
    const uint32_t sa1 = smem_u32(&sA[0][(srow + 64) * SPITCH + sq]);
    const uint32_t sb0 = smem_u32(&sB[0][srow * SPITCH + sq]);
    const uint32_t sb1 = smem_u32(&sB[0][(srow + 64) * SPITCH + sq]);
    const uint32_t bufB = 128 * SPITCH * 4;   // bytes per buffer

    // ldmatrix per-lane addresses (buffer 0 base).
    // A x4 (one ks): lanes 0-7 rows r+0..7 @k0 | 8-15 rows+8 @k0
    //               | 16-23 rows @k0+4 | 24-31 rows+8 @k0+4
    const int la_row = (lid & 7) + ((lid >> 3) & 1) * 8;
    const int la_col = (lid >> 4) * 4;
    uint32_t aAddr[4];
    #pragma unroll
    for (int mt = 0; mt < 4; mt++)
        aAddr[mt] = smem_u32(&sA[0][(wm + mt * 16 + la_row) * SPITCH + la_col]);
    // B x4 (both ks): lanes (lid>>3)=s -> k group s*4; rows n+0..7
    const int lb_row = lid & 7;
    const int lb_col = (lid >> 3) * 4;
    uint32_t bAddr[4];
    #pragma unroll
    for (int nt = 0; nt < 4; nt++)
        bAddr[nt] = smem_u32(&sB[0][(wn + nt * 8 + lb_row) * SPITCH + lb_col]);

    float acc[4][4][4];
    #pragma unroll
    for (int mt = 0; mt < 4; mt++)
        #pragma unroll
        for (int nt = 0; nt < 4; nt++)
            #pragma unroll
            for (int r = 0; r < 4; r++) acc[mt][nt][r] = 0.0f;

    const int nch = Kdim / BKC;

    // prologue: stage chunk 0 into buffer 0
    {
        CP_ASYNC16(sa0, Ag0); CP_ASYNC16(sa1, Ag1);
        CP_ASYNC16(sb0, Bg0); CP_ASYNC16(sb1, Bg1);
        CP_COMMIT;
    }

    for (int c = 0; c < nch; c++) {
        CP_WAIT0;                 // chunk c complete (this thread's group)
        __syncthreads();          // publish chunk c; compute(c-1) done by all
        if (c + 1 < nch) {        // stage chunk c+1 into the freed buffer
            const int koff = (c + 1) * BKC;
            const uint32_t bs = ((c + 1) & 1) * bufB;
            CP_ASYNC16(sa0 + bs, Ag0 + koff);
            CP_ASYNC16(sa1 + bs, Ag1 + koff);
            CP_ASYNC16(sb0 + bs, Bg0 + koff);
            CP_ASYNC16(sb1 + bs, Bg1 + koff);
            CP_COMMIT;
        }

        const uint32_t boff = (c & 1) * bufB;
        uint32_t bfr[4][4];
        #pragma unroll
        for (int nt = 0; nt < 4; nt++)
            LDSM_X4(bfr[nt][0], bfr[nt][1], bfr[nt][2], bfr[nt][3],
                    bAddr[nt] + boff);
        #pragma unroll
        for (int ks = 0; ks < 2; ks++) {
            uint32_t afr[4][4];
            #pragma unroll
            for (int mt = 0; mt < 4; mt++)
                LDSM_X4(afr[mt][0], afr[mt][1], afr[mt][2], afr[mt][3],
                        aAddr[mt] + boff + ks * 32);
            #pragma unroll
            for (int mt = 0; mt < 4; mt++)
                #pragma unroll
                for (int nt = 0; nt < 4; nt++)
                    MMA_TF32(acc[mt][nt],
                             afr[mt][0], afr[mt][1], afr[mt][2], afr[mt][3],
                             bfr[nt][2 * ks], bfr[nt][2 * ks + 1]);
        }
    }

    // Epilogue
    #pragma unroll
    for (int mt = 0; mt < 4; mt++) {
        const int r0 = m0 + wm + mt * 16 + lm;
        const int r1 = r0 + 8;
        float rs0 = 1.0f, rs1 = 1.0f;
        if (rowscale) { rs0 = rowscale[r0]; rs1 = rowscale[r1]; }
        #pragma unroll
        for (int nt = 0; nt < 4; nt++) {
            const int col = n0 + wn + nt * 8 + lk * 2;
            float2 bb = *(const float2*)&bias[col];
            float v0 = acc[mt][nt][0] * rs0 + bb.x;
            float v1 = acc[mt][nt][1] * rs0 + bb.y;
            float v2 = acc[mt][nt][2] * rs1 + bb.x;
            float v3 = acc[mt][nt][3] * rs1 + bb.y;
            if (EPI == 1) {
                v0 = f2tf32f(fmaxf(v0, 0.0f));
                v1 = f2tf32f(fmaxf(v1, 0.0f));
                v2 = f2tf32f(fmaxf(v2, 0.0f));
                v3 = f2tf32f(fmaxf(v3, 0.0f));
            }
            if (EPI == 2) {
                float2 q0 = *(const float2*)&res[(size_t)r0 * Ndim + col];
                float2 q1 = *(const float2*)&res[(size_t)r1 * Ndim + col];
                v0 += q0.x; v1 += q0.y; v2 += q1.x; v3 += q1.y;
            }
            *(float2*)&C[(size_t)r0 * Ndim + col] = make_float2(v0, v1);
            *(float2*)&C[(size_t)r1 * Ndim + col] = make_float2(v2, v3);
        }
    }
}

// ---------------------------------------------------------------------------
// Tensor-core flash attention (tf32 mma.sync). R9/R12-proven; ctx rounded
// to tf32 in the epilogue (feeds the Wo GEMM which now expects tf32 input).
// ---------------------------------------------------------------------------
#define MMA_TF32A(c, a, b) \
    asm volatile("mma.sync.aligned.m16n8k8.row.col.f32.tf32.tf32.f32 " \
        "{%0,%1,%2,%3}, {%4,%5,%6,%7}, {%8,%9}, {%0,%1,%2,%3};" \
        : "+f"((c)[0]), "+f"((c)[1]), "+f"((c)[2]), "+f"((c)[3]) \
        : "r"((a)[0]), "r"((a)[1]), "r"((a)[2]), "r"((a)[3]), \
          "r"((b)[0]), "r"((b)[1]))

__global__ void __launch_bounds__(128)
attn_tc_kernel(const float* __restrict__ q, const float* __restrict__ k,
               const float* __restrict__ v, float* __restrict__ ctx) {
    __shared__ float sK[64 * KPITCH];    // K tile [s][d]; Q staged here first
    __shared__ float sV[64 * VPITCH];    // V tile [s][d] (natural)

    const int tid = threadIdx.x;
    const int wid = tid >> 5;
    const int lid = tid & 31;
    const int g   = lid >> 2;        // 0..7 fragment row group
    const int t   = lid & 3;         // 0..3 thread-in-quad
    const int t0  = blockIdx.x * 64;
    const int h   = blockIdx.y;
    const int b   = blockIdx.z;
    const size_t rs = (size_t)BB * EE;
    const float* qb = q + (size_t)b * EE + h * HK;
    const float* kb = k + (size_t)b * EE + h * HK;
    const float* vb = v + (size_t)b * EE + h * HK;
    float* cb = ctx + (size_t)b * EE + h * HK;

    // Stage Q (pre-scaled by 1/8 — exact power of 2 — then tf32-rounded)
    #pragma unroll
    for (int p = 0; p < 8; p++) {
        int s   = tid + p * 128;
        int row = s >> 4;
        int c4  = (s & 15) * 4;
        float4 vq = *(const float4*)&qb[(size_t)(t0 + row) * rs + c4];
        sK[row * KPITCH + c4 + 0] = f2tf32f(vq.x * 0.125f);
        sK[row * KPITCH + c4 + 1] = f2tf32f(vq.y * 0.125f);
        sK[row * KPITCH + c4 + 2] = f2tf32f(vq.z * 0.125f);
        sK[row * KPITCH + c4 + 3] = f2tf32f(vq.w * 0.125f);
    }
    __syncthreads();

    // Q fragments for rows wid*16+g, +8 (register-resident all kernel)
    uint32_t qf[8][4];
    #pragma unroll
    for (int kk = 0; kk < 8; kk++) {
        const float* ap = sK + (wid * 16 + g) * KPITCH + kk * 8 + t;
        qf[kk][0] = __float_as_uint(ap[0]);
        qf[kk][1] = __float_as_uint(ap[8 * KPITCH]);
        qf[kk][2] = __float_as_uint(ap[4]);
        qf[kk][3] = __float_as_uint(ap[8 * KPITCH + 4]);
    }

    float mx0 = -INFINITY, mx1 = -INFINITY, l0 = 0.0f, l1 = 0.0f;
    float o[8][4];
    #pragma unroll
    for (int dd = 0; dd < 8; dd++)
        #pragma unroll
        for (int r = 0; r < 4; r++) o[dd][r] = 0.0f;

    const int l0lane = (lid & 28) | (t >> 1);
    const int l2lane = l0lane | 2;
    const bool odd = t & 1;

    for (int s0 = 0; s0 < TT; s0 += 64) {
        __syncthreads();   // previous tile reads done (covers Q-frag reads too)
        // Stage K [s][d] and V [s][d], tf32-rounded
        #pragma unroll
        for (int p = 0; p < 8; p++) {
            int s   = tid + p * 128;
            int row = s >> 4;
            int c4  = (s & 15) * 4;
            float4 kv = *(const float4*)&kb[(size_t)(s0 + row) * rs + c4];
            sK[row * KPITCH + c4 + 0] = f2tf32f(kv.x);
            sK[row * KPITCH + c4 + 1] = f2tf32f(kv.y);
            sK[row * KPITCH + c4 + 2] = f2tf32f(kv.z);
            sK[row * KPITCH + c4 + 3] = f2tf32f(kv.w);
            float4 vv = *(const float4*)&vb[(size_t)(s0 + row) * rs + c4];
            sV[row * VPITCH + c4 + 0] = f2tf32f(vv.x);
            sV[row * VPITCH + c4 + 1] = f2tf32f(vv.y);
            sV[row * VPITCH + c4 + 2] = f2tf32f(vv.z);
            sV[row * VPITCH + c4 + 3] = f2tf32f(vv.w);
        }
        __syncthreads();

        // S = Q K^T (m16 x n64 per warp)
        float sc[8][4];
        #pragma unroll
        for (int nt = 0; nt < 8; nt++) {
            float c[4] = {0.0f, 0.0f, 0.0f, 0.0f};
            #pragma unroll
            for (int kk = 0; kk < 8; kk++) {
                const float* bp = sK + (nt * 8 + g) * KPITCH + kk * 8 + t;
                uint32_t bf[2] = {__float_as_uint(bp[0]), __float_as_uint(bp[4])};
                MMA_TF32A(c, qf[kk], bf);
            }
            sc[nt][0] = c[0]; sc[nt][1] = c[1]; sc[nt][2] = c[2]; sc[nt][3] = c[3];
        }

        // Online softmax (rows g, g+8)
        float rmax0 = -INFINITY, rmax1 = -INFINITY;
        #pragma unroll
        for (int nt = 0; nt < 8; nt++) {
            rmax0 = fmaxf(rmax0, fmaxf(sc[nt][0], sc[nt][1]));
            rmax1 = fmaxf(rmax1, fmaxf(sc[nt][2], sc[nt][3]));
        }
        rmax0 = fmaxf(rmax0, __shfl_xor_sync(0xffffffffu, rmax0, 1));
        rmax0 = fmaxf(rmax0, __shfl_xor_sync(0xffffffffu, rmax0, 2));
        rmax1 = fmaxf(rmax1, __shfl_xor_sync(0xffffffffu, rmax1, 1));
        rmax1 = fmaxf(rmax1, __shfl_xor_sync(0xffffffffu, rmax1, 2));
        float mn0 = fmaxf(mx0, rmax0), mn1 = fmaxf(mx1, rmax1);
        float corr0 = __expf(mx0 - mn0), corr1 = __expf(mx1 - mn1);
        mx0 = mn0; mx1 = mn1;
        float s0sum = 0.0f, s1sum = 0.0f;
        #pragma unroll
        for (int nt = 0; nt < 8; nt++) {
            sc[nt][0] = __expf(sc[nt][0] - mn0);
            sc[nt][1] = __expf(sc[nt][1] - mn0);
            sc[nt][2] = __expf(sc[nt][2] - mn1);
            sc[nt][3] = __expf(sc[nt][3] - mn1);
            s0sum += sc[nt][0] + sc[nt][1];
            s1sum += sc[nt][2] + sc[nt][3];
        }
        s0sum += __shfl_xor_sync(0xffffffffu, s0sum, 1);
        s0sum += __shfl_xor_sync(0xffffffffu, s0sum, 2);
        s1sum += __shfl_xor_sync(0xffffffffu, s1sum, 1);
        s1sum += __shfl_xor_sync(0xffffffffu, s1sum, 2);
        l0 = l0 * corr0 + s0sum;
        l1 = l1 * corr1 + s1sum;
        #pragma unroll
        for (int dd = 0; dd < 8; dd++) {
            o[dd][0] *= corr0; o[dd][1] *= corr0;
            o[dd][2] *= corr1; o[dd][3] *= corr1;
        }

        // O += P V: re-fragment P via quad shuffles, read V naturally
        #pragma unroll
        for (int kk = 0; kk < 8; kk++) {
            float p0 = sc[kk][0], p1 = sc[kk][1], p2 = sc[kk][2], p3 = sc[kk][3];
            float x00 = __shfl_sync(0xffffffffu, p0, l0lane);
            float x01 = __shfl_sync(0xffffffffu, p1, l0lane);
            float x02 = __shfl_sync(0xffffffffu, p2, l0lane);
            float x03 = __shfl_sync(0xffffffffu, p3, l0lane);
            float x20 = __shfl_sync(0xffffffffu, p0, l2lane);
            float x21 = __shfl_sync(0xffffffffu, p1, l2lane);
            float x22 = __shfl_sync(0xffffffffu, p2, l2lane);
            float x23 = __shfl_sync(0xffffffffu, p3, l2lane);
            uint32_t af[4];
            af[0] = f2tf32(odd ? x01 : x00);
            af[1] = f2tf32(odd ? x03 : x02);
            af[2] = f2tf32(odd ? x21 : x20);
            af[3] = f2tf32(odd ? x23 : x22);
            const float* vrow0 = sV + (kk * 8 + t) * VPITCH;
            const float* vrow1 = sV + (kk * 8 + t + 4) * VPITCH;
            #pragma unroll
            for (int dd = 0; dd < 8; dd++) {
                uint32_t bf[2] = {__float_as_uint(vrow0[dd * 8 + g]),
                                  __float_as_uint(vrow1[dd * 8 + g])};
                MMA_TF32A(o[dd], af, bf);
            }
        }
    }

    // Finalize: ctx = O / l (tf32-rounded for the Wo GEMM)
    const float inv0 = 1.0f / l0, inv1 = 1.0f / l1;
    const int row0 = t0 + wid * 16 + g;
    const int row1 = row0 + 8;
    #pragma unroll
    for (int dd = 0; dd < 8; dd++) {
        const int col = dd * 8 + t * 2;
        *(float2*)&cb[(size_t)row0 * rs + col] =
            make_float2(f2tf32f(o[dd][0] * inv0), f2tf32f(o[dd][1] * inv0));
        *(float2*)&cb[(size_t)row1 * rs + col] =
            make_float2(f2tf32f(o[dd][2] * inv1), f2tf32f(o[dd][3] * inv1));
    }
}

// ---------------------------------------------------------------------------
// LayerNorm over E=1024, one block (256 threads) per row.
// Optional second output = tf32-rounded copy.
// ---------------------------------------------------------------------------
__device__ __forceinline__ float block_reduce_sum(float v) {
    #pragma unroll
    for (int o = 16; o > 0; o >>= 1) v += __shfl_xor_sync(0xffffffffu, v, o);
    __shared__ float red[8];
    __shared__ float tot;
    int w = threadIdx.x >> 5;
    if ((threadIdx.x & 31) == 0) red[w] = v;
    __syncthreads();
    if (threadIdx.x == 0) {
        float t = 0.0f;
        #pragma unroll
        for (int i = 0; i < 8; i++) t += red[i];
        tot = t;
    }
    __syncthreads();
    return tot;
}

__global__ void __launch_bounds__(256)
ln_kernel(const float* __restrict__ x, const float* __restrict__ gamma,
          const float* __restrict__ beta, float* __restrict__ y,
          float* __restrict__ yr) {
    const int row = blockIdx.x;
    const int tid = threadIdx.x;
    float4 v = *(const float4*)&x[(size_t)row * EE + tid * 4];
    float s = v.x + v.y + v.z + v.w;
    float mu = block_reduce_sum(s) * (1.0f / EE);
    float dx = v.x - mu, dy = v.y - mu, dz = v.z - mu, dw = v.w - mu;
    float sq = dx * dx + dy * dy + dz * dz + dw * dw;
    float var = block_reduce_sum(sq) * (1.0f / EE);
    float rstd = rsqrtf(var + LN_EPS);
    float4 g = *(const float4*)&gamma[tid * 4];
    float4 b = *(const float4*)&beta[tid * 4];
    float4 o;
    o.x = dx * rstd * g.x + b.x;
    o.y = dy * rstd * g.y + b.y;
    o.z = dz * rstd * g.z + b.z;
    o.w = dw * rstd * g.w + b.w;
    *(float4*)&y[(size_t)row * EE + tid * 4] = o;
    if (yr) {
        float4 r = make_float4(f2tf32f(o.x), f2tf32f(o.y),
                               f2tf32f(o.z), f2tf32f(o.w));
        *(float4*)&yr[(size_t)row * EE + tid * 4] = r;
    }
}

// ---------------------------------------------------------------------------
// Launch
// ---------------------------------------------------------------------------
extern "C" void kernel_launch(void* const* d_in, const int* in_sizes, int n_in,
                              void* d_out, int out_size) {
    (void)in_sizes; (void)n_in; (void)out_size;
    const float* state = (const float*)d_in[0];
    const void*  mask  = d_in[1];
    const float* Wq = (const float*)d_in[2];
    const float* bq = (const float*)d_in[3];
    const float* Wk = (const float*)d_in[4];
    const float* bk = (const float*)d_in[5];
    const float* Wv = (const float*)d_in[6];
    const float* bv = (const float*)d_in[7];
    const float* Wo = (const float*)d_in[8];
    const float* bo = (const float*)d_in[9];
    const float* ln1g = (const float*)d_in[10];
    const float* ln1b = (const float*)d_in[11];
    const float* W1 = (const float*)d_in[12];
    const float* b1 = (const float*)d_in[13];
    const float* W2 = (const float*)d_in[14];
    const float* b2 = (const float*)d_in[15];
    const float* ln2g = (const float*)d_in[16];
    const float* ln2b = (const float*)d_in[17];
    float* out = (float*)d_out;

    float *qp, *kp, *vp, *cp, *t1, *s1f, *s1r, *hd, *t2, *keep;
    float *rstate, *rwq, *rwk, *rwv, *rwo, *rw1, *rw2;
    cudaGetSymbolAddress((void**)&qp,     g_q);
    cudaGetSymbolAddress((void**)&kp,     g_k);
    cudaGetSymbolAddress((void**)&vp,     g_v);
    cudaGetSymbolAddress((void**)&cp,     g_ctx);
    cudaGetSymbolAddress((void**)&t1,     g_t1);
    cudaGetSymbolAddress((void**)&s1f,    g_s1f);
    cudaGetSymbolAddress((void**)&s1r,    g_s1r);
    cudaGetSymbolAddress((void**)&hd,     g_hid);
    cudaGetSymbolAddress((void**)&t2,     g_t2);
    cudaGetSymbolAddress((void**)&keep,   g_keep);
    cudaGetSymbolAddress((void**)&rstate, g_rstate);
    cudaGetSymbolAddress((void**)&rwq,    g_rwq);
    cudaGetSymbolAddress((void**)&rwk,    g_rwk);
    cudaGetSymbolAddress((void**)&rwv,    g_rwv);
    cudaGetSymbolAddress((void**)&rwo,    g_rwo);
    cudaGetSymbolAddress((void**)&rw1,    g_rw1);
    cudaGetSymbolAddress((void**)&rw2,    g_rw2);

    detect_mask_kernel<<<1, 256>>>((const unsigned char*)mask);
    build_keep_kernel<<<MM / 256, 256>>>(mask);

    // tf32 pre-rounding (rna) of all GEMM operands
    const int RT = 256;
    round_tf32_kernel<<<(MM * EE / 4) / RT, RT>>>(state, rstate, MM * EE / 4);
    round_tf32_kernel<<<(EE * EE / 4) / RT, RT>>>(Wq, rwq, EE * EE / 4);
    round_tf32_kernel<<<(EE * EE / 4) / RT, RT>>>(Wk, rwk, EE * EE / 4);
    round_tf32_kernel<<<(EE * EE / 4) / RT, RT>>>(Wv, rwv, EE * EE / 4);
    round_tf32_kernel<<<(EE * EE / 4) / RT, RT>>>(Wo, rwo, EE * EE / 4);
    round_tf32_kernel<<<(FFD * EE / 4) / RT, RT>>>(W1, rw1, FFD * EE / 4);
    round_tf32_kernel<<<(FFD * EE / 4) / RT, RT>>>(W2, rw2, FFD * EE / 4);

    dim3 gE(EE / 128, MM / 128);     // (8, 32)
    dim3 gF(FFD / 128, MM / 128);    // (32, 32)

    // Projections (key mask as epilogue rowscale on K projection)
    gemm_mma_kernel<0><<<gE, 256>>>(rstate, rwq, bq, nullptr, nullptr, qp, EE, EE);
    gemm_mma_kernel<0><<<gE, 256>>>(rstate, rwk, bk, keep,    nullptr, kp, EE, EE);
    gemm_mma_kernel<0><<<gE, 256>>>(rstate, rwv, bv, nullptr, nullptr, vp, EE, EE);

    // Attention (tensor-core flash; rounds ctx for the Wo GEMM)
    attn_tc_kernel<<<dim3(TT / 64, HH, BB), 128>>>(qp, kp, vp, cp);

    // O projection + residual, LN1 (dual output: f32 + rounded)
    gemm_mma_kernel<2><<<gE, 256>>>(cp, rwo, bo, nullptr, state, t1, EE, EE);
    ln_kernel<<<MM, 256>>>(t1, ln1g, ln1b, s1f, s1r);

    // FFN
    gemm_mma_kernel<1><<<gF, 256>>>(s1r, rw1, b1, nullptr, nullptr, hd, FFD, EE);
    gemm_mma_kernel<2><<<gE, 256>>>(hd, rw2, b2, nullptr, s1f, t2, EE, FFD);

    // LN2 -> output
    ln_kernel<<<MM, 256>>>(t2, ln2g, ln2b, out, nullptr);
}

// round 15
// speedup vs baseline: 1.6136x; 1.1171x over previous
#include <cuda_runtime.h>
#include <cuda_bf16.h>
#include <cstdint>
#include <cstddef>

// Problem constants
#define TT 2048
#define BB 2
#define EE 1024
#define HH 16
#define HK 64          // head dim
#define FFD 4096
#define MM (TT*BB)     // 4096 rows
#define LN_EPS 1e-5f
#define BKC 16         // GEMM K chunk
#define P16 16         // GEMM smem pitch (floats), XOR-swizzled groups
#define STAGEB 8192u   // bytes per matrix per stage (128*16*4)
#define KPITCH 68      // attention K-tile pitch
#define VPITCH 72      // attention V-tile pitch

// ---------------------------------------------------------------------------
// Scratch (device globals; no allocation allowed)
// ---------------------------------------------------------------------------
__device__ float g_keep[MM];
__device__ int   g_maskmode;
__device__ float g_q[MM * EE];
__device__ float g_k[MM * EE];
__device__ float g_v[MM * EE];
__device__ float g_ctx[MM * EE];     // tf32-rounded by attention epilogue
__device__ float g_t1[MM * EE];
__device__ float g_s1f[MM * EE];     // LN1 out, f32 (residual)
__device__ float g_s1r[MM * EE];     // LN1 out, tf32-rounded (FFN1 A)
__device__ float g_hid[(size_t)MM * FFD];  // tf32-rounded by FFN1 epilogue
__device__ float g_t2[MM * EE];
__device__ float g_rstate[MM * EE];  // tf32-rounded state
__device__ float g_rwq[EE * EE];
__device__ float g_rwk[EE * EE];
__device__ float g_rwv[EE * EE];
__device__ float g_rwo[EE * EE];
__device__ float g_rw1[(size_t)FFD * EE];
__device__ float g_rw2[(size_t)FFD * EE];

// ---------------------------------------------------------------------------
// Helpers
// ---------------------------------------------------------------------------
__device__ __forceinline__ uint32_t smem_u32(const void* p) {
    uint32_t a;
    asm("{ .reg .u64 t; cvta.to.shared.u64 t, %1; cvt.u32.u64 %0, t; }"
        : "=r"(a) : "l"(p));
    return a;
}

__device__ __forceinline__ uint32_t f2tf32(float x) {
    uint32_t r;
    asm("cvt.rna.tf32.f32 %0, %1;" : "=r"(r) : "f"(x));
    return r;
}
__device__ __forceinline__ float f2tf32f(float x) {
    return __uint_as_float(f2tf32(x));
}

#define CP_ASYNC16(dst_u32, src_ptr) \
    asm volatile("cp.async.cg.shared.global [%0], [%1], 16;" \
                 :: "r"(dst_u32), "l"(src_ptr) : "memory")
#define CP_COMMIT asm volatile("cp.async.commit_group;" ::: "memory")
#define CP_WAIT1  asm volatile("cp.async.wait_group 1;" ::: "memory")
#define CP_WAIT0  asm volatile("cp.async.wait_group 0;" ::: "memory")

#define MMA_TF32(c, a0, a1, a2, a3, b0, b1) \
    asm volatile("mma.sync.aligned.m16n8k8.row.col.f32.tf32.tf32.f32 " \
        "{%0,%1,%2,%3}, {%4,%5,%6,%7}, {%8,%9}, {%0,%1,%2,%3};" \
        : "+f"((c)[0]), "+f"((c)[1]), "+f"((c)[2]), "+f"((c)[3]) \
        : "r"(a0), "r"(a1), "r"(a2), "r"(a3), "r"(b0), "r"(b1))

#define LDSM_X4(r0, r1, r2, r3, addr) \
    asm volatile("ldmatrix.sync.aligned.m8n8.x4.shared.b16 {%0,%1,%2,%3}, [%4];" \
        : "=r"(r0), "=r"(r1), "=r"(r2), "=r"(r3) : "r"(addr))

// Swizzled float index of (row, 16B-group g): row*16 + (g ^ ((row>>1)&3))*4
__device__ __forceinline__ int swidx(int row, int g) {
    return row * P16 + ((g ^ ((row >> 1) & 3)) << 2);
}

// ---------------------------------------------------------------------------
// Mask dtype detection + keep vector
// ---------------------------------------------------------------------------
__global__ void detect_mask_kernel(const unsigned char* __restrict__ mask) {
    __shared__ int cnt[4];
    if (threadIdx.x < 4) cnt[threadIdx.x] = 0;
    __syncthreads();
    for (int i = threadIdx.x; i < BB * TT; i += blockDim.x) {
        if (mask[i]) atomicAdd(&cnt[i & 3], 1);
    }
    __syncthreads();
    if (threadIdx.x == 0) {
        int mode;
        if (cnt[1] > 0)                    mode = 0;  // bytes
        else if (cnt[2] > 0 || cnt[3] > 0) mode = 2;  // float32
        else if (cnt[0] > 0)               mode = 1;  // int32
        else                               mode = 3;  // all zero
        g_maskmode = mode;
    }
}

__global__ void build_keep_kernel(const void* __restrict__ mask) {
    int m = blockIdx.x * blockDim.x + threadIdx.x;
    if (m >= MM) return;
    int t = m >> 1;
    int b = m & 1;
    int idx = b * TT + t;
    int mode = g_maskmode;
    bool pad;
    if (mode == 0)      pad = ((const unsigned char*)mask)[idx] != 0;
    else if (mode == 1) pad = ((const int*)mask)[idx] != 0;
    else if (mode == 2) pad = ((const float*)mask)[idx] != 0.0f;
    else                pad = false;
    g_keep[m] = pad ? 0.0f : 1.0f;
}

// ---------------------------------------------------------------------------
// tf32 rounding pass (rna)
// ---------------------------------------------------------------------------
__global__ void round_tf32_kernel(const float* __restrict__ in,
                                  float* __restrict__ out, int n4) {
    int i = blockIdx.x * blockDim.x + threadIdx.x;
    if (i >= n4) return;
    float4 v = ((const float4*)in)[i];
    v.x = f2tf32f(v.x); v.y = f2tf32f(v.y);
    v.z = f2tf32f(v.z); v.w = f2tf32f(v.w);
    ((float4*)out)[i] = v;
}

// ---------------------------------------------------------------------------
// tf32 mma.sync NT GEMM:  C[M,N] = epi( rowscale[m]*(A[M,K]*B[N,K]^T) + bias[N] )
//   EPI 0: + bias; EPI 1: + bias, ReLU, round; EPI 2: + bias + residual
// A and B MUST be pre-rounded tf32 values (mainloop has zero ALU work).
// CTA tile 128x128, BK=16, 8 warps (2Mx4N), warp 64x32, m16n8k8.
// 3-stage cp.async pipeline (48KB static smem exactly), prefetch depth 2,
// ONE syncthreads per chunk. Pitch-16 XOR-swizzled smem:
//   group g of row r stored at g ^ ((r>>1)&3)  -> conflict-free for both
//   the 16B cp.async stores (optimal 4 phases) and all ldmatrix reads
//   (8 rows hit the 8 distinct (parity,group) bank slots).
// Fragment loads via ldmatrix.m8n8.x4.b16; per-lane addresses precomputed.
// ---------------------------------------------------------------------------
template <int EPI>
__global__ void __launch_bounds__(256, 2)
gemm_mma_kernel(const float* __restrict__ A, const float* __restrict__ Bw,
                const float* __restrict__ bias, const float* __restrict__ rowscale,
                const float* __restrict__ res, float* __restrict__ C,
                int Ndim, int Kdim) {
    __shared__ __align__(16) float sA[3][128 * P16];
    __shared__ __align__(16) float sB[3][128 * P16];

    const int tid = threadIdx.x;
    const int wid = tid >> 5;
    const int lid = tid & 31;
    const int m0 = blockIdx.y * 128;
    const int n0 = blockIdx.x * 128;
    const int wm = (wid >> 2) * 64;   // warp M offset
    const int wn = (wid & 3) * 32;    // warp N offset
    const int lm = lid >> 2;          // 0..7
    const int lk = lid & 3;           // 0..3

    // Staging geometry: thread covers rows srow, srow+64; 16B group gs.
    const int srow = tid >> 2;        // 0..63
    const int gs   = tid & 3;         // 0..3
    const float* Ag0 = A  + (size_t)(m0 + srow)      * Kdim + gs * 4;
    const float* Ag1 = A  + (size_t)(m0 + srow + 64) * Kdim + gs * 4;
    const float* Bg0 = Bw + (size_t)(n0 + srow)      * Kdim + gs * 4;
    const float* Bg1 = Bw + (size_t)(n0 + srow + 64) * Kdim + gs * 4;
    const uint32_t sa0 = smem_u32(&sA[0][swidx(srow,      gs)]);
    const uint32_t sa1 = smem_u32(&sA[0][swidx(srow + 64, gs)]);
    const uint32_t sb0 = smem_u32(&sB[0][swidx(srow,      gs)]);
    const uint32_t sb1 = smem_u32(&sB[0][swidx(srow + 64, gs)]);

    // ldmatrix per-lane addresses (stage 0 base).
    const int la_row = (lid & 7) + ((lid >> 3) & 1) * 8;
    const int la_g   = lid >> 4;          // 0 or 1
    uint32_t aAddr[4][2];
    #pragma unroll
    for (int mt = 0; mt < 4; mt++)
        #pragma unroll
        for (int ks = 0; ks < 2; ks++)
            aAddr[mt][ks] = smem_u32(
                &sA[0][swidx(wm + mt * 16 + la_row, la_g + 2 * ks)]);
    const int lb_row = lid & 7;
    const int lb_g   = lid >> 3;          // 0..3
    uint32_t bAddr[4];
    #pragma unroll
    for (int nt = 0; nt < 4; nt++)
        bAddr[nt] = smem_u32(&sB[0][swidx(wn + nt * 8 + lb_row, lb_g)]);

    float acc[4][4][4];
    #pragma unroll
    for (int mt = 0; mt < 4; mt++)
        #pragma unroll
        for (int nt = 0; nt < 4; nt++)
            #pragma unroll
            for (int r = 0; r < 4; r++) acc[mt][nt][r] = 0.0f;

    const int nch = Kdim / BKC;

    // Prologue: stage chunks 0 (stage 0) and 1 (stage 1)
    {
        CP_ASYNC16(sa0, Ag0); CP_ASYNC16(sa1, Ag1);
        CP_ASYNC16(sb0, Bg0); CP_ASYNC16(sb1, Bg1);
        CP_COMMIT;
        CP_ASYNC16(sa0 + STAGEB, Ag0 + BKC);
        CP_ASYNC16(sa1 + STAGEB, Ag1 + BKC);
        CP_ASYNC16(sb0 + STAGEB, Bg0 + BKC);
        CP_ASYNC16(sb1 + STAGEB, Bg1 + BKC);
        CP_COMMIT;
    }

    uint32_t soC = 0;            // stage byte offset of chunk c
    uint32_t soI = 2 * STAGEB;   // stage byte offset of chunk c+2

    for (int c = 0; c < nch; c++) {
        if (c + 1 < nch) { CP_WAIT1; } else { CP_WAIT0; }
        __syncthreads();          // chunk c visible; stage (c+2)%3 free
        if (c + 2 < nch) {
            const int koff = (c + 2) * BKC;
            CP_ASYNC16(sa0 + soI, Ag0 + koff);
            CP_ASYNC16(sa1 + soI, Ag1 + koff);
            CP_ASYNC16(sb0 + soI, Bg0 + koff);
            CP_ASYNC16(sb1 + soI, Bg1 + koff);
            CP_COMMIT;
            soI += STAGEB; if (soI == 3 * STAGEB) soI = 0;
        }

        uint32_t bfr[4][4];
        #pragma unroll
        for (int nt = 0; nt < 4; nt++)
            LDSM_X4(bfr[nt][0], bfr[nt][1], bfr[nt][2], bfr[nt][3],
                    bAddr[nt] + soC);
        #pragma unroll
        for (int ks = 0; ks < 2; ks++) {
            uint32_t afr[4][4];
            #pragma unroll
            for (int mt = 0; mt < 4; mt++)
                LDSM_X4(afr[mt][0], afr[mt][1], afr[mt][2], afr[mt][3],
                        aAddr[mt][ks] + soC);
            #pragma unroll
            for (int mt = 0; mt < 4; mt++)
                #pragma unroll
                for (int nt = 0; nt < 4; nt++)
                    MMA_TF32(acc[mt][nt],
                             afr[mt][0], afr[mt][1], afr[mt][2], afr[mt][3],
                             bfr[nt][2 * ks], bfr[nt][2 * ks + 1]);
        }
        soC += STAGEB; if (soC == 3 * STAGEB) soC = 0;
    }

    // Epilogue
    #pragma unroll
    for (int mt = 0; mt < 4; mt++) {
        const int r0 = m0 + wm + mt * 16 + lm;
        const int r1 = r0 + 8;
        float rs0 = 1.0f, rs1 = 1.0f;
        if (rowscale) { rs0 = rowscale[r0]; rs1 = rowscale[r1]; }
        #pragma unroll
        for (int nt = 0; nt < 4; nt++) {
            const int col = n0 + wn + nt * 8 + lk * 2;
            float2 bb = *(const float2*)&bias[col];
            float v0 = acc[mt][nt][0] * rs0 + bb.x;
            float v1 = acc[mt][nt][1] * rs0 + bb.y;
            float v2 = acc[mt][nt][2] * rs1 + bb.x;
            float v3 = acc[mt][nt][3] * rs1 + bb.y;
            if (EPI == 1) {
                v0 = f2tf32f(fmaxf(v0, 0.0f));
                v1 = f2tf32f(fmaxf(v1, 0.0f));
                v2 = f2tf32f(fmaxf(v2, 0.0f));
                v3 = f2tf32f(fmaxf(v3, 0.0f));
            }
            if (EPI == 2) {
                float2 q0 = *(const float2*)&res[(size_t)r0 * Ndim + col];
                float2 q1 = *(const float2*)&res[(size_t)r1 * Ndim + col];
                v0 += q0.x; v1 += q0.y; v2 += q1.x; v3 += q1.y;
            }
            *(float2*)&C[(size_t)r0 * Ndim + col] = make_float2(v0, v1);
            *(float2*)&C[(size_t)r1 * Ndim + col] = make_float2(v2, v3);
        }
    }
}

// ---------------------------------------------------------------------------
// Tensor-core flash attention (tf32 mma.sync). Unchanged from R13-passing.
// ---------------------------------------------------------------------------
#define MMA_TF32A(c, a, b) \
    asm volatile("mma.sync.aligned.m16n8k8.row.col.f32.tf32.tf32.f32 " \
        "{%0,%1,%2,%3}, {%4,%5,%6,%7}, {%8,%9}, {%0,%1,%2,%3};" \
        : "+f"((c)[0]), "+f"((c)[1]), "+f"((c)[2]), "+f"((c)[3]) \
        : "r"((a)[0]), "r"((a)[1]), "r"((a)[2]), "r"((a)[3]), \
          "r"((b)[0]), "r"((b)[1]))

__global__ void __launch_bounds__(128)
attn_tc_kernel(const float* __restrict__ q, const float* __restrict__ k,
               const float* __restrict__ v, float* __restrict__ ctx) {
    __shared__ float sK[64 * KPITCH];    // K tile [s][d]; Q staged here first
    __shared__ float sV[64 * VPITCH];    // V tile [s][d] (natural)

    const int tid = threadIdx.x;
    const int wid = tid >> 5;
    const int lid = tid & 31;
    const int g   = lid >> 2;        // 0..7 fragment row group
    const int t   = lid & 3;         // 0..3 thread-in-quad
    const int t0  = blockIdx.x * 64;
    const int h   = blockIdx.y;
    const int b   = blockIdx.z;
    const size_t rs = (size_t)BB * EE;
    const float* qb = q + (size_t)b * EE + h * HK;
    const float* kb = k + (size_t)b * EE + h * HK;
    const float* vb = v + (size_t)b * EE + h * HK;
    float* cb = ctx + (size_t)b * EE + h * HK;

    // Stage Q (pre-scaled by 1/8 — exact power of 2 — then tf32-rounded)
    #pragma unroll
    for (int p = 0; p < 8; p++) {
        int s   = tid + p * 128;
        int row = s >> 4;
        int c4  = (s & 15) * 4;
        float4 vq = *(const float4*)&qb[(size_t)(t0 + row) * rs + c4];
        sK[row * KPITCH + c4 + 0] = f2tf32f(vq.x * 0.125f);
        sK[row * KPITCH + c4 + 1] = f2tf32f(vq.y * 0.125f);
        sK[row * KPITCH + c4 + 2] = f2tf32f(vq.z * 0.125f);
        sK[row * KPITCH + c4 + 3] = f2tf32f(vq.w * 0.125f);
    }
    __syncthreads();

    // Q fragments for rows wid*16+g, +8 (register-resident all kernel)
    uint32_t qf[8][4];
    #pragma unroll
    for (int kk = 0; kk < 8; kk++) {
        const float* ap = sK + (wid * 16 + g) * KPITCH + kk * 8 + t;
        qf[kk][0] = __float_as_uint(ap[0]);
        qf[kk][1] = __float_as_uint(ap[8 * KPITCH]);
        qf[kk][2] = __float_as_uint(ap[4]);
        qf[kk][3] = __float_as_uint(ap[8 * KPITCH + 4]);
    }

    float mx0 = -INFINITY, mx1 = -INFINITY, l0 = 0.0f, l1 = 0.0f;
    float o[8][4];
    #pragma unroll
    for (int dd = 0; dd < 8; dd++)
        #pragma unroll
        for (int r = 0; r < 4; r++) o[dd][r] = 0.0f;

    const int l0lane = (lid & 28) | (t >> 1);
    const int l2lane = l0lane | 2;
    const bool odd = t & 1;

    for (int s0 = 0; s0 < TT; s0 += 64) {
        __syncthreads();   // previous tile reads done (covers Q-frag reads too)
        // Stage K [s][d] and V [s][d], tf32-rounded
        #pragma unroll
        for (int p = 0; p < 8; p++) {
            int s   = tid + p * 128;
            int row = s >> 4;
            int c4  = (s & 15) * 4;
            float4 kv = *(const float4*)&kb[(size_t)(s0 + row) * rs + c4];
            sK[row * KPITCH + c4 + 0] = f2tf32f(kv.x);
            sK[row * KPITCH + c4 + 1] = f2tf32f(kv.y);
            sK[row * KPITCH + c4 + 2] = f2tf32f(kv.z);
            sK[row * KPITCH + c4 + 3] = f2tf32f(kv.w);
            float4 vv = *(const float4*)&vb[(size_t)(s0 + row) * rs + c4];
            sV[row * VPITCH + c4 + 0] = f2tf32f(vv.x);
            sV[row * VPITCH + c4 + 1] = f2tf32f(vv.y);
            sV[row * VPITCH + c4 + 2] = f2tf32f(vv.z);
            sV[row * VPITCH + c4 + 3] = f2tf32f(vv.w);
        }
        __syncthreads();

        // S = Q K^T (m16 x n64 per warp)
        float sc[8][4];
        #pragma unroll
        for (int nt = 0; nt < 8; nt++) {
            float c[4] = {0.0f, 0.0f, 0.0f, 0.0f};
            #pragma unroll
            for (int kk = 0; kk < 8; kk++) {
                const float* bp = sK + (nt * 8 + g) * KPITCH + kk * 8 + t;
                uint32_t bf[2] = {__float_as_uint(bp[0]), __float_as_uint(bp[4])};
                MMA_TF32A(c, qf[kk], bf);
            }
            sc[nt][0] = c[0]; sc[nt][1] = c[1]; sc[nt][2] = c[2]; sc[nt][3] = c[3];
        }

        // Online softmax (rows g, g+8)
        float rmax0 = -INFINITY, rmax1 = -INFINITY;
        #pragma unroll
        for (int nt = 0; nt < 8; nt++) {
            rmax0 = fmaxf(rmax0, fmaxf(sc[nt][0], sc[nt][1]));
            rmax1 = fmaxf(rmax1, fmaxf(sc[nt][2], sc[nt][3]));
        }
        rmax0 = fmaxf(rmax0, __shfl_xor_sync(0xffffffffu, rmax0, 1));
        rmax0 = fmaxf(rmax0, __shfl_xor_sync(0xffffffffu, rmax0, 2));
        rmax1 = fmaxf(rmax1, __shfl_xor_sync(0xffffffffu, rmax1, 1));
        rmax1 = fmaxf(rmax1, __shfl_xor_sync(0xffffffffu, rmax1, 2));
        float mn0 = fmaxf(mx0, rmax0), mn1 = fmaxf(mx1, rmax1);
        float corr0 = __expf(mx0 - mn0), corr1 = __expf(mx1 - mn1);
        mx0 = mn0; mx1 = mn1;
        float s0sum = 0.0f, s1sum = 0.0f;
        #pragma unroll
        for (int nt = 0; nt < 8; nt++) {
            sc[nt][0] = __expf(sc[nt][0] - mn0);
            sc[nt][1] = __expf(sc[nt][1] - mn0);
            sc[nt][2] = __expf(sc[nt][2] - mn1);
            sc[nt][3] = __expf(sc[nt][3] - mn1);
            s0sum += sc[nt][0] + sc[nt][1];
            s1sum += sc[nt][2] + sc[nt][3];
        }
        s0sum += __shfl_xor_sync(0xffffffffu, s0sum, 1);
        s0sum += __shfl_xor_sync(0xffffffffu, s0sum, 2);
        s1sum += __shfl_xor_sync(0xffffffffu, s1sum, 1);
        s1sum += __shfl_xor_sync(0xffffffffu, s1sum, 2);
        l0 = l0 * corr0 + s0sum;
        l1 = l1 * corr1 + s1sum;
        #pragma unroll
        for (int dd = 0; dd < 8; dd++) {
            o[dd][0] *= corr0; o[dd][1] *= corr0;
            o[dd][2] *= corr1; o[dd][3] *= corr1;
        }

        // O += P V: re-fragment P via quad shuffles, read V naturally
        #pragma unroll
        for (int kk = 0; kk < 8; kk++) {
            float p0 = sc[kk][0], p1 = sc[kk][1], p2 = sc[kk][2], p3 = sc[kk][3];
            float x00 = __shfl_sync(0xffffffffu, p0, l0lane);
            float x01 = __shfl_sync(0xffffffffu, p1, l0lane);
            float x02 = __shfl_sync(0xffffffffu, p2, l0lane);
            float x03 = __shfl_sync(0xffffffffu, p3, l0lane);
            float x20 = __shfl_sync(0xffffffffu, p0, l2lane);
            float x21 = __shfl_sync(0xffffffffu, p1, l2lane);
            float x22 = __shfl_sync(0xffffffffu, p2, l2lane);
            float x23 = __shfl_sync(0xffffffffu, p3, l2lane);
            uint32_t af[4];
            af[0] = f2tf32(odd ? x01 : x00);
            af[1] = f2tf32(odd ? x03 : x02);
            af[2] = f2tf32(odd ? x21 : x20);
            af[3] = f2tf32(odd ? x23 : x22);
            const float* vrow0 = sV + (kk * 8 + t) * VPITCH;
            const float* vrow1 = sV + (kk * 8 + t + 4) * VPITCH;
            #pragma unroll
            for (int dd = 0; dd < 8; dd++) {
                uint32_t bf[2] = {__float_as_uint(vrow0[dd * 8 + g]),
                                  __float_as_uint(vrow1[dd * 8 + g])};
                MMA_TF32A(o[dd], af, bf);
            }
        }
    }

    // Finalize: ctx = O / l (tf32-rounded for the Wo GEMM)
    const float inv0 = 1.0f / l0, inv1 = 1.0f / l1;
    const int row0 = t0 + wid * 16 + g;
    const int row1 = row0 + 8;
    #pragma unroll
    for (int dd = 0; dd < 8; dd++) {
        const int col = dd * 8 + t * 2;
        *(float2*)&cb[(size_t)row0 * rs + col] =
            make_float2(f2tf32f(o[dd][0] * inv0), f2tf32f(o[dd][1] * inv0));
        *(float2*)&cb[(size_t)row1 * rs + col] =
            make_float2(f2tf32f(o[dd][2] * inv1), f2tf32f(o[dd][3] * inv1));
    }
}

// ---------------------------------------------------------------------------
// LayerNorm over E=1024, one block (256 threads) per row.
// Optional second output = tf32-rounded copy.
// ---------------------------------------------------------------------------
__device__ __forceinline__ float block_reduce_sum(float v) {
    #pragma unroll
    for (int o = 16; o > 0; o >>= 1) v += __shfl_xor_sync(0xffffffffu, v, o);
    __shared__ float red[8];
    __shared__ float tot;
    int w = threadIdx.x >> 5;
    if ((threadIdx.x & 31) == 0) red[w] = v;
    __syncthreads();
    if (threadIdx.x == 0) {
        float t = 0.0f;
        #pragma unroll
        for (int i = 0; i < 8; i++) t += red[i];
        tot = t;
    }
    __syncthreads();
    return tot;
}

__global__ void __launch_bounds__(256)
ln_kernel(const float* __restrict__ x, const float* __restrict__ gamma,
          const float* __restrict__ beta, float* __restrict__ y,
          float* __restrict__ yr) {
    const int row = blockIdx.x;
    const int tid = threadIdx.x;
    float4 v = *(const float4*)&x[(size_t)row * EE + tid * 4];
    float s = v.x + v.y + v.z + v.w;
    float mu = block_reduce_sum(s) * (1.0f / EE);
    float dx = v.x - mu, dy = v.y - mu, dz = v.z - mu, dw = v.w - mu;
    float sq = dx * dx + dy * dy + dz * dz + dw * dw;
    float var = block_reduce_sum(sq) * (1.0f / EE);
    float rstd = rsqrtf(var + LN_EPS);
    float4 g = *(const float4*)&gamma[tid * 4];
    float4 b = *(const float4*)&beta[tid * 4];
    float4 o;
    o.x = dx * rstd * g.x + b.x;
    o.y = dy * rstd * g.y + b.y;
    o.z = dz * rstd * g.z + b.z;
    o.w = dw * rstd * g.w + b.w;
    *(float4*)&y[(size_t)row * EE + tid * 4] = o;
    if (yr) {
        float4 r = make_float4(f2tf32f(o.x), f2tf32f(o.y),
                               f2tf32f(o.z), f2tf32f(o.w));
        *(float4*)&yr[(size_t)row * EE + tid * 4] = r;
    }
}

// ---------------------------------------------------------------------------
// Launch
// ---------------------------------------------------------------------------
extern "C" void kernel_launch(void* const* d_in, const int* in_sizes, int n_in,
                              void* d_out, int out_size) {
    (void)in_sizes; (void)n_in; (void)out_size;
    const float* state = (const float*)d_in[0];
    const void*  mask  = d_in[1];
    const float* Wq = (const float*)d_in[2];
    const float* bq = (const float*)d_in[3];
    const float* Wk = (const float*)d_in[4];
    const float* bk = (const float*)d_in[5];
    const float* Wv = (const float*)d_in[6];
    const float* bv = (const float*)d_in[7];
    const float* Wo = (const float*)d_in[8];
    const float* bo = (const float*)d_in[9];
    const float* ln1g = (const float*)d_in[10];
    const float* ln1b = (const float*)d_in[11];
    const float* W1 = (const float*)d_in[12];
    const float* b1 = (const float*)d_in[13];
    const float* W2 = (const float*)d_in[14];
    const float* b2 = (const float*)d_in[15];
    const float* ln2g = (const float*)d_in[16];
    const float* ln2b = (const float*)d_in[17];
    float* out = (float*)d_out;

    float *qp, *kp, *vp, *cp, *t1, *s1f, *s1r, *hd, *t2, *keep;
    float *rstate, *rwq, *rwk, *rwv, *rwo, *rw1, *rw2;
    cudaGetSymbolAddress((void**)&qp,     g_q);
    cudaGetSymbolAddress((void**)&kp,     g_k);
    cudaGetSymbolAddress((void**)&vp,     g_v);
    cudaGetSymbolAddress((void**)&cp,     g_ctx);
    cudaGetSymbolAddress((void**)&t1,     g_t1);
    cudaGetSymbolAddress((void**)&s1f,    g_s1f);
    cudaGetSymbolAddress((void**)&s1r,    g_s1r);
    cudaGetSymbolAddress((void**)&hd,     g_hid);
    cudaGetSymbolAddress((void**)&t2,     g_t2);
    cudaGetSymbolAddress((void**)&keep,   g_keep);
    cudaGetSymbolAddress((void**)&rstate, g_rstate);
    cudaGetSymbolAddress((void**)&rwq,    g_rwq);
    cudaGetSymbolAddress((void**)&rwk,    g_rwk);
    cudaGetSymbolAddress((void**)&rwv,    g_rwv);
    cudaGetSymbolAddress((void**)&rwo,    g_rwo);
    cudaGetSymbolAddress((void**)&rw1,    g_rw1);
    cudaGetSymbolAddress((void**)&rw2,    g_rw2);

    detect_mask_kernel<<<1, 256>>>((const unsigned char*)mask);
    build_keep_kernel<<<MM / 256, 256>>>(mask);

    // tf32 pre-rounding (rna) of all GEMM operands
    const int RT = 256;
    round_tf32_kernel<<<(MM * EE / 4) / RT, RT>>>(state, rstate, MM * EE / 4);
    round_tf32_kernel<<<(EE * EE / 4) / RT, RT>>>(Wq, rwq, EE * EE / 4);
    round_tf32_kernel<<<(EE * EE / 4) / RT, RT>>>(Wk, rwk, EE * EE / 4);
    round_tf32_kernel<<<(EE * EE / 4) / RT, RT>>>(Wv, rwv, EE * EE / 4);
    round_tf32_kernel<<<(EE * EE / 4) / RT, RT>>>(Wo, rwo, EE * EE / 4);
    round_tf32_kernel<<<(FFD * EE / 4) / RT, RT>>>(W1, rw1, FFD * EE / 4);
    round_tf32_kernel<<<(FFD * EE / 4) / RT, RT>>>(W2, rw2, FFD * EE / 4);

    dim3 gE(EE / 128, MM / 128);     // (8, 32)
    dim3 gF(FFD / 128, MM / 128);    // (32, 32)

    // Projections (key mask as epilogue rowscale on K projection)
    gemm_mma_kernel<0><<<gE, 256>>>(rstate, rwq, bq, nullptr, nullptr, qp, EE, EE);
    gemm_mma_kernel<0><<<gE, 256>>>(rstate, rwk, bk, keep,    nullptr, kp, EE, EE);
    gemm_mma_kernel<0><<<gE, 256>>>(rstate, rwv, bv, nullptr, nullptr, vp, EE, EE);

    // Attention (tensor-core flash; rounds ctx for the Wo GEMM)
    attn_tc_kernel<<<dim3(TT / 64, HH, BB), 128>>>(qp, kp, vp, cp);

    // O projection + residual, LN1 (dual output: f32 + rounded)
    gemm_mma_kernel<2><<<gE, 256>>>(cp, rwo, bo, nullptr, state, t1, EE, EE);
    ln_kernel<<<MM, 256>>>(t1, ln1g, ln1b, s1f, s1r);

    // FFN
    gemm_mma_kernel<1><<<gF, 256>>>(s1r, rw1, b1, nullptr, nullptr, hd, FFD, EE);
    gemm_mma_kernel<2><<<gE, 256>>>(hd, rw2, b2, nullptr, s1f, t2, EE, FFD);

    // LN2 -> output
    ln_kernel<<<MM, 256>>>(t2, ln2g, ln2b, out, nullptr);
}